// round 13
// baseline (speedup 1.0000x reference)
#include <cuda_runtime.h>
#include <cuda_fp16.h>
#include <cstdint>

#define N0 8000
#define N1 4000
#define N2 2000
#define DIM 128
#define XW 384
#define ASCALE 2048.0f
#define AINV (1.0f / 2048.0f)

// Xt = X^T [384][N_i], fp16 (single plane)
__device__ __half g_Bh0[XW * N0];
__device__ __half g_Bh1[XW * N1];
__device__ __half g_Bh2[XW * N2];
// fp32 Y = ASCALE * (adj @ X)
__device__ float g_Y0[N0 * XW];
__device__ float g_Y1[N1 * XW];
__device__ float g_Y2[N2 * XW];

// ===========================================================================
// helpers
// ===========================================================================
__device__ __forceinline__ uint32_t smem_to_u32(const void* p) {
    uint32_t a;
    asm("{ .reg .u64 t; cvta.to.shared.u64 t, %1; cvt.u32.u64 %0, t; }" : "=r"(a) : "l"(p));
    return a;
}
__device__ __forceinline__ void ldsm4(uint32_t* r, uint32_t addr) {
    asm volatile("ldmatrix.sync.aligned.m8n8.x4.shared.b16 {%0,%1,%2,%3}, [%4];"
                 : "=r"(r[0]), "=r"(r[1]), "=r"(r[2]), "=r"(r[3]) : "r"(addr));
}
__device__ __forceinline__ void mma16816(float* c, const uint32_t* a, const uint32_t* b) {
    asm volatile(
        "mma.sync.aligned.m16n8k16.row.col.f32.f16.f16.f32 "
        "{%0,%1,%2,%3}, {%4,%5,%6,%7}, {%8,%9}, {%0,%1,%2,%3};"
        : "+f"(c[0]), "+f"(c[1]), "+f"(c[2]), "+f"(c[3])
        : "r"(a[0]), "r"(a[1]), "r"(a[2]), "r"(a[3]), "r"(b[0]), "r"(b[1]));
}
__device__ __forceinline__ void cpa16(uint32_t d, const void* s, int sz) {
    asm volatile("cp.async.cg.shared.global [%0], [%1], 16, %2;"
                 :: "r"(d), "l"(s), "r"(sz) : "memory");
}
#define CP_COMMIT() asm volatile("cp.async.commit_group;" ::: "memory")
#define CP_WAIT2() asm volatile("cp.async.wait_group 2;" ::: "memory")

__device__ __forceinline__ uint32_t pkh2(__half x, __half y) {
    __half2 t;
    t.x = x; t.y = y;
    return reinterpret_cast<uint32_t&>(t);
}

// ===========================================================================
// Zero of scatter-target B regions
// ===========================================================================
__global__ void k_zero_all(float4* __restrict__ a0, float4* __restrict__ a1) {
    int i = blockIdx.x * blockDim.x + threadIdx.x;
    int st = gridDim.x * blockDim.x;
    float4 z = make_float4(0.f, 0.f, 0.f, 0.f);
    for (int k = i; k < 256000; k += st) a0[k] = z;
    for (int k = i; k < 64000; k += st) a1[k] = z;
}

// ===========================================================================
// Fused transposed placement: Xt[rowOff+f][r] = H[chain(r)][f] (fp16)
// ===========================================================================
__device__ __forceinline__ void trans_blk(float (*tile)[33],
                                          __half* __restrict__ Bh, int ld,
                                          const float* __restrict__ H, int rows,
                                          const int* __restrict__ s1,
                                          const int* __restrict__ s2, int rowOff, int blk) {
    int tid = threadIdx.x;
    int r0 = blk * 32;
#pragma unroll
    for (int t = 0; t < 4; t++) {
        int g = tid + t * 256;
        int r = g >> 5;
        int c4 = g & 31;
        int sr = r0 + r;
        float4 v = make_float4(0.f, 0.f, 0.f, 0.f);
        if (sr < rows) {
            int s = sr;
            if (s2) s = s2[s];
            if (s1) s = s1[s];
            v = *reinterpret_cast<const float4*>(H + (size_t)s * DIM + c4 * 4);
        }
        tile[c4 * 4 + 0][r] = v.x;
        tile[c4 * 4 + 1][r] = v.y;
        tile[c4 * 4 + 2][r] = v.z;
        tile[c4 * 4 + 3][r] = v.w;
    }
    __syncthreads();
    int f = tid >> 1;
    int half = tid & 1;
#pragma unroll
    for (int m4 = 0; m4 < 4; m4++) {
        int lc = half * 16 + m4 * 4;
        int col = r0 + lc;
        if (col < rows) {
            uint2 h;
            h.x = pkh2(__float2half_rn(tile[f][lc]), __float2half_rn(tile[f][lc + 1]));
            h.y = pkh2(__float2half_rn(tile[f][lc + 2]), __float2half_rn(tile[f][lc + 3]));
            *reinterpret_cast<uint2*>(Bh + (size_t)(rowOff + f) * ld + col) = h;
        }
    }
}

__global__ __launch_bounds__(256) void k_trans_all(
    __half* Bh0p, __half* Bh1p, __half* Bh2p,
    const float* h0, const float* h1, const float* h2,
    const int* idx0, const int* idx1) {
    __shared__ float tile[128][33];
    int b = blockIdx.x;
    if (b < 250)      trans_blk(tile, Bh0p, N0, h0, N0, nullptr, nullptr, 0, b);
    else if (b < 375) trans_blk(tile, Bh1p, N1, h0, N1, idx0, nullptr, 0, b - 250);
    else if (b < 500) trans_blk(tile, Bh1p, N1, h1, N1, nullptr, nullptr, 128, b - 375);
    else if (b < 563) trans_blk(tile, Bh2p, N2, h0, N2, idx0, idx1, 0, b - 500);
    else if (b < 626) trans_blk(tile, Bh2p, N2, h1, N2, idx1, nullptr, 128, b - 563);
    else              trans_blk(tile, Bh2p, N2, h2, N2, nullptr, nullptr, 256, b - 626);
}

// ===========================================================================
// Fused scattered placement (up path), fp16
// ===========================================================================
__device__ __forceinline__ void scat_row(__half* __restrict__ Bh, int ld,
                                         const float* __restrict__ H,
                                         const int* __restrict__ d1,
                                         const int* __restrict__ d2, int rowOff,
                                         int r, int f) {
    float v = H[(size_t)r * DIM + f];
    int dr = r;
    if (d2) dr = d2[dr];
    if (d1) dr = d1[dr];
    Bh[(size_t)(rowOff + f) * ld + dr] = __float2half_rn(v);
}

__global__ __launch_bounds__(256) void k_scatter_all(
    __half* Bh0p, __half* Bh1p,
    const float* h1, const float* h2, const int* idx0, const int* idx1) {
    int b = blockIdx.x;
    int f = threadIdx.x & 127;
    int rh = threadIdx.x >> 7;
    if (b < 2000)      scat_row(Bh0p, N0, h1, idx0, nullptr, 128, b * 2 + rh, f);
    else if (b < 3000) scat_row(Bh0p, N0, h2, idx0, idx1, 256, (b - 2000) * 2 + rh, f);
    else               scat_row(Bh1p, N1, h2, idx1, nullptr, 256, (b - 3000) * 2 + rh, f);
}

// ===========================================================================
// fp16 1-term mma.sync GEMM with FUSED in-kernel A conversion.
// A arrives fp32 via cp.async (8KB/stage); block-level convert (x ASCALE) into
// one shared fp16 A buffer (ldsm swizzle), then ldmatrix+HMMA as before.
// Stage: Araw fp32 8K | Bh fp16 8K = 16384 B x 4 stages + AFP16 4K = 69632 B.
// Grid: 660 CTAs single launch, 2 CTAs/SM.
// ===========================================================================
#define OFF_ARAW 0
#define OFF_BH 8192
#define STAGE_BYTES 16384
#define OFF_AFP16 65536
#define SMEM_MMA 69632

__device__ __forceinline__ void issue_stage(
    uint32_t stg, const float* __restrict__ A, const __half* __restrict__ Bh,
    int rowBase, int nBase, int M, int ld, int gk0, int Klim, int tid) {
    // A fp32: 64 rows x 128B (8 chunks of 16B), flat layout
#pragma unroll
    for (int i = 0; i < 2; i++) {
        int t = tid + i * 256;            // 0..511
        int row = t >> 3, c16 = t & 7;
        int gk = gk0 + c16 * 4;
        const float* src = A + (size_t)(rowBase + row) * ld + gk;
        uint32_t d = stg + OFF_ARAW + row * 128 + c16 * 16;
        int p = (rowBase + row < M && gk < Klim) ? 16 : 0;
        cpa16(d, src, p);
    }
    // B fp16: 128 rows x 4 chunks of 16B, xor-swizzled for ldsm
#pragma unroll
    for (int i = 0; i < 2; i++) {
        int t = tid + i * 256;
        int row = t >> 2, c = t & 3;
        int gk = gk0 + c * 8;
        size_t so = (size_t)(nBase + row) * ld + gk;
        uint32_t d = stg + OFF_BH + row * 64 + ((c ^ ((row >> 1) & 3)) << 4);
        int p = (gk < Klim) ? 16 : 0;
        cpa16(d, Bh + so, p);
    }
}

__global__ __launch_bounds__(256, 2)
void k_mma(const float* __restrict__ A0, const float* __restrict__ A1,
           const float* __restrict__ A2,
           const __half* __restrict__ Bh0p, const __half* __restrict__ Bh1p,
           const __half* __restrict__ Bh2p,
           float* __restrict__ Y0, float* __restrict__ Y1, float* __restrict__ Y2) {
    extern __shared__ char sm[];
    int tid = threadIdx.x;
    int lane = tid & 31;
    int wid = tid >> 5;
    int bx = blockIdx.x;

    const float* A;
    const __half* Bh;
    float* Y;
    int M, ld, mt, nt, nIter, Klim;
    if (bx < 375) {
        mt = bx / 3; nt = bx % 3;
        A = A0; Bh = Bh0p; Y = Y0;
        M = N0; ld = N0; nIter = 250; Klim = N0;
    } else if (bx < 564) {
        int t = bx - 375;
        mt = t / 3; nt = t % 3;
        A = A1; Bh = Bh1p; Y = Y1;
        M = N1; ld = N1; nIter = 125; Klim = N1;
    } else {
        int t = bx - 564;
        mt = t / 3; nt = t % 3;
        A = A2; Bh = Bh2p; Y = Y2;
        M = N2; ld = N2; nIter = 63; Klim = N2;
    }
    int rowBase = mt * 64;
    int nBase = nt * 128;

    uint32_t sbase = smem_to_u32(sm);
    int wm = wid & 1;    // 2 m-warps x 32 rows
    int wn = wid >> 1;   // 4 n-warps x 32 cols

    // Convert-thread geometry: row = tid>>2 (0..63), c = tid&3 (8 floats each)
    int cvRow = tid >> 2;
    int cvC = tid & 3;
    uint32_t cvSrc = OFF_ARAW + cvRow * 128 + cvC * 32;
    uint32_t cvDst = OFF_AFP16 + cvRow * 64 + ((cvC ^ ((cvRow >> 1) & 3)) << 4);

    // ldmatrix geometry
    int rA = lane & 15;
    int cA = lane >> 4;
    int rBl = (lane & 7) + ((lane >> 4) & 1) * 8;
    int cB = (lane >> 3) & 1;
    uint32_t arow[2], aswz[2], brow[2], bswz[2];
#pragma unroll
    for (int mi = 0; mi < 2; mi++) {
        int r = wm * 32 + mi * 16 + rA;
        arow[mi] = (uint32_t)r * 64;
        aswz[mi] = (r >> 1) & 3;
    }
#pragma unroll
    for (int nb = 0; nb < 2; nb++) {
        int r = wn * 32 + nb * 16 + rBl;
        brow[nb] = (uint32_t)r * 64;
        bswz[nb] = (r >> 1) & 3;
    }

    float acc[2][4][4];
#pragma unroll
    for (int mi = 0; mi < 2; mi++)
#pragma unroll
        for (int ni = 0; ni < 4; ni++)
#pragma unroll
            for (int c = 0; c < 4; c++) acc[mi][ni][c] = 0.f;

#pragma unroll
    for (int s = 0; s < 3; s++) {
        issue_stage(sbase + s * STAGE_BYTES, A, Bh, rowBase, nBase, M, ld,
                    s * 32, Klim, tid);
        CP_COMMIT();
    }

    for (int it = 0; it < nIter; it++) {
        CP_WAIT2();
        __syncthreads();
        if (it + 3 < nIter)
            issue_stage(sbase + ((it + 3) & 3) * STAGE_BYTES, A, Bh,
                        rowBase, nBase, M, ld, (it + 3) * 32, Klim, tid);
        CP_COMMIT();

        uint32_t stg = sbase + (it & 3) * STAGE_BYTES;

        // --- Block-level A convert: fp32 (flat) -> fp16 scaled (ldsm swizzle) ---
        {
            const char* smc = sm + (it & 3) * STAGE_BYTES;
            float4 a0 = *reinterpret_cast<const float4*>(smc + cvSrc);
            float4 a1 = *reinterpret_cast<const float4*>(smc + cvSrc + 16);
            uint4 h;
            h.x = pkh2(__float2half_rn(a0.x * ASCALE), __float2half_rn(a0.y * ASCALE));
            h.y = pkh2(__float2half_rn(a0.z * ASCALE), __float2half_rn(a0.w * ASCALE));
            h.z = pkh2(__float2half_rn(a1.x * ASCALE), __float2half_rn(a1.y * ASCALE));
            h.w = pkh2(__float2half_rn(a1.z * ASCALE), __float2half_rn(a1.w * ASCALE));
            *reinterpret_cast<uint4*>(sm + cvDst) = h;
        }
        __syncthreads();

#pragma unroll
        for (int k16 = 0; k16 < 2; k16++) {
            uint32_t ah[2][4], bh[2][4];
#pragma unroll
            for (int mi = 0; mi < 2; mi++) {
                uint32_t off = arow[mi] + ((((uint32_t)(k16 * 2 + cA)) ^ aswz[mi]) << 4);
                ldsm4(ah[mi], sbase + OFF_AFP16 + off);
            }
#pragma unroll
            for (int nb = 0; nb < 2; nb++) {
                uint32_t off = brow[nb] + ((((uint32_t)(k16 * 2 + cB)) ^ bswz[nb]) << 4);
                ldsm4(bh[nb], stg + OFF_BH + off);
            }
#pragma unroll
            for (int mi = 0; mi < 2; mi++)
#pragma unroll
                for (int nb = 0; nb < 2; nb++) {
                    mma16816(acc[mi][2 * nb], ah[mi], &bh[nb][0]);
                    mma16816(acc[mi][2 * nb + 1], ah[mi], &bh[nb][2]);
                }
        }
    }

    int colB = nBase + wn * 32 + (lane & 3) * 2;
#pragma unroll
    for (int mi = 0; mi < 2; mi++)
#pragma unroll
        for (int h = 0; h < 2; h++) {
            int row = rowBase + wm * 32 + mi * 16 + (lane >> 2) + h * 8;
            if (row < M) {
                float* yp = Y + (size_t)row * XW + colB;
#pragma unroll
                for (int ni = 0; ni < 4; ni++)
                    *reinterpret_cast<float2*>(yp + ni * 8) =
                        make_float2(acc[mi][ni][2 * h], acc[mi][ni][2 * h + 1]);
            }
        }
}

// ===========================================================================
// Fused fp32 epilogue; Y is scaled by ASCALE -> unscale on load.
// ===========================================================================
__global__ __launch_bounds__(256) void k_epi(const float* __restrict__ Y0a,
                                             const float* __restrict__ Y1a,
                                             const float* __restrict__ Y2a,
                                             const float* __restrict__ Wall,
                                             const float* __restrict__ ball,
                                             float* __restrict__ outAll) {
    __shared__ float As[16][132];
    __shared__ float Bs[16][128];
    int tid = threadIdx.x;
    int tx = tid & 15;
    int ty = tid >> 4;
    int bx = blockIdx.x;

    const float* Y;
    float* out;
    int M, ilev, mt;
    if (bx < 63) {
        Y = Y0a; out = outAll; M = N0; ilev = 0; mt = bx;
    } else if (bx < 95) {
        Y = Y1a; out = outAll + (size_t)N0 * DIM; M = N1; ilev = 1; mt = bx - 63;
    } else {
        Y = Y2a; out = outAll + (size_t)(N0 + N1) * DIM; M = N2; ilev = 2; mt = bx - 95;
    }
    int rowBase = mt * 128;

    float sum[8][8];
#pragma unroll
    for (int i = 0; i < 8; i++)
#pragma unroll
        for (int j = 0; j < 8; j++) sum[i][j] = 0.f;

    for (int jb = 0; jb < 3; jb++) {
        const float* W = Wall + (size_t)(ilev * 3 + jb) * DIM * DIM;
        float acc[8][8];
#pragma unroll
        for (int i = 0; i < 8; i++)
#pragma unroll
            for (int j = 0; j < 8; j++) acc[i][j] = 0.f;

        for (int k0 = 0; k0 < DIM; k0 += 16) {
#pragma unroll
            for (int l = 0; l < 2; l++) {
                int s = tid + l * 256;
                int r = s >> 2;
                int kq = (s & 3) * 4;
                int grow = rowBase + r;
                float4 v = make_float4(0.f, 0.f, 0.f, 0.f);
                if (grow < M) {
                    v = *reinterpret_cast<const float4*>(Y + (size_t)grow * XW + jb * DIM + k0 + kq);
                    v.x *= AINV; v.y *= AINV; v.z *= AINV; v.w *= AINV;
                }
                As[kq + 0][r] = v.x;
                As[kq + 1][r] = v.y;
                As[kq + 2][r] = v.z;
                As[kq + 3][r] = v.w;
            }
#pragma unroll
            for (int l = 0; l < 2; l++) {
                int s = tid + l * 256;
                int kr = s >> 5;
                int c4 = (s & 31) * 4;
                *reinterpret_cast<float4*>(&Bs[kr][c4]) =
                    *reinterpret_cast<const float4*>(W + (size_t)(k0 + kr) * DIM + c4);
            }
            __syncthreads();
#pragma unroll
            for (int kk = 0; kk < 16; kk++) {
                float a[8], b[8];
                *reinterpret_cast<float4*>(a) = *reinterpret_cast<const float4*>(&As[kk][ty * 8]);
                *reinterpret_cast<float4*>(a + 4) = *reinterpret_cast<const float4*>(&As[kk][ty * 8 + 4]);
                *reinterpret_cast<float4*>(b) = *reinterpret_cast<const float4*>(&Bs[kk][tx * 8]);
                *reinterpret_cast<float4*>(b + 4) = *reinterpret_cast<const float4*>(&Bs[kk][tx * 8 + 4]);
#pragma unroll
                for (int i = 0; i < 8; i++)
#pragma unroll
                    for (int j = 0; j < 8; j++) acc[i][j] += a[i] * b[j];
            }
            __syncthreads();
        }
        const float* bvec = ball + (size_t)(ilev * 3 + jb) * DIM;
#pragma unroll
        for (int j = 0; j < 8; j++) {
            float bb = bvec[tx * 8 + j];
#pragma unroll
            for (int i = 0; i < 8; i++) sum[i][j] += fmaxf(acc[i][j] + bb, 0.f);
        }
    }

#pragma unroll
    for (int i = 0; i < 8; i++) {
        int grow = rowBase + ty * 8 + i;
        if (grow < M) {
            float* op = out + (size_t)grow * DIM + tx * 8;
            *reinterpret_cast<float4*>(op) = make_float4(sum[i][0], sum[i][1], sum[i][2], sum[i][3]);
            *reinterpret_cast<float4*>(op + 4) = make_float4(sum[i][4], sum[i][5], sum[i][6], sum[i][7]);
        }
    }
}

// ===========================================================================
extern "C" void kernel_launch(void* const* d_in, const int* in_sizes, int n_in,
                              void* d_out, int out_size) {
    const float* adj0 = (const float*)d_in[0];
    const float* adj1 = (const float*)d_in[1];
    const float* adj2 = (const float*)d_in[2];
    const float* h0 = (const float*)d_in[3];
    const float* h1 = (const float*)d_in[4];
    const float* h2 = (const float*)d_in[5];
    const int* idx0 = (const int*)d_in[6];
    const int* idx1 = (const int*)d_in[7];
    const float* Ws = (const float*)d_in[8];
    const float* bs = (const float*)d_in[9];
    float* out = (float*)d_out;

    __half *Bh0, *Bh1, *Bh2;
    float *Y0, *Y1, *Y2;
    cudaGetSymbolAddress((void**)&Bh0, g_Bh0);
    cudaGetSymbolAddress((void**)&Bh1, g_Bh1);
    cudaGetSymbolAddress((void**)&Bh2, g_Bh2);
    cudaGetSymbolAddress((void**)&Y0, g_Y0);
    cudaGetSymbolAddress((void**)&Y1, g_Y1);
    cudaGetSymbolAddress((void**)&Y2, g_Y2);

    cudaFuncSetAttribute(k_mma, cudaFuncAttributeMaxDynamicSharedMemorySize, SMEM_MMA);

    // 1. Zero scatter-target B regions
    k_zero_all<<<640, 256>>>((float4*)(Bh0 + (size_t)128 * N0),
                             (float4*)(Bh1 + (size_t)256 * N1));

    // 2. Build Xt fp16
    k_trans_all<<<689, 256>>>(Bh0, Bh1, Bh2, h0, h1, h2, idx0, idx1);
    k_scatter_all<<<4000, 256>>>(Bh0, Bh1, h1, h2, idx0, idx1);

    // 3. Y_i = ASCALE * adj_i @ X_i — fp16 GEMM with fused A conversion
    k_mma<<<660, 256, SMEM_MMA>>>(adj0, adj1, adj2, Bh0, Bh1, Bh2, Y0, Y1, Y2);

    // 4. Fused epilogue (unscales Y)
    k_epi<<<111, 256>>>(Y0, Y1, Y2, Ws, bs, out);
}

// round 14
// speedup vs baseline: 1.0162x; 1.0162x over previous
#include <cuda_runtime.h>
#include <cuda_fp16.h>
#include <cstdint>

#define N0 8000
#define N1 4000
#define N2 2000
#define DIM 128
#define XW 384
#define ASCALE 2048.0f
#define AINV (1.0f / 2048.0f)

// Xt = X^T [384][N_i], fp16 (single plane)
__device__ __half g_Bh0[XW * N0];
__device__ __half g_Bh1[XW * N1];
__device__ __half g_Bh2[XW * N2];
// fp32 Y = ASCALE * (adj @ X)
__device__ float g_Y0[N0 * XW];
__device__ float g_Y1[N1 * XW];
__device__ float g_Y2[N2 * XW];

// ===========================================================================
// helpers
// ===========================================================================
__device__ __forceinline__ uint32_t smem_to_u32(const void* p) {
    uint32_t a;
    asm("{ .reg .u64 t; cvta.to.shared.u64 t, %1; cvt.u32.u64 %0, t; }" : "=r"(a) : "l"(p));
    return a;
}
__device__ __forceinline__ void ldsm4(uint32_t* r, uint32_t addr) {
    asm volatile("ldmatrix.sync.aligned.m8n8.x4.shared.b16 {%0,%1,%2,%3}, [%4];"
                 : "=r"(r[0]), "=r"(r[1]), "=r"(r[2]), "=r"(r[3]) : "r"(addr));
}
__device__ __forceinline__ void mma16816(float* c, const uint32_t* a, const uint32_t* b) {
    asm volatile(
        "mma.sync.aligned.m16n8k16.row.col.f32.f16.f16.f32 "
        "{%0,%1,%2,%3}, {%4,%5,%6,%7}, {%8,%9}, {%0,%1,%2,%3};"
        : "+f"(c[0]), "+f"(c[1]), "+f"(c[2]), "+f"(c[3])
        : "r"(a[0]), "r"(a[1]), "r"(a[2]), "r"(a[3]), "r"(b[0]), "r"(b[1]));
}
__device__ __forceinline__ void cpa16(uint32_t d, const void* s, int sz) {
    asm volatile("cp.async.cg.shared.global [%0], [%1], 16, %2;"
                 :: "r"(d), "l"(s), "r"(sz) : "memory");
}
#define CP_COMMIT() asm volatile("cp.async.commit_group;" ::: "memory")
#define CP_WAIT2() asm volatile("cp.async.wait_group 2;" ::: "memory")

__device__ __forceinline__ uint32_t pkh2(__half x, __half y) {
    __half2 t;
    t.x = x; t.y = y;
    return reinterpret_cast<uint32_t&>(t);
}

// ===========================================================================
// Zero of scatter-target B regions
// ===========================================================================
__global__ void k_zero_all(float4* __restrict__ a0, float4* __restrict__ a1) {
    int i = blockIdx.x * blockDim.x + threadIdx.x;
    int st = gridDim.x * blockDim.x;
    float4 z = make_float4(0.f, 0.f, 0.f, 0.f);
    for (int k = i; k < 256000; k += st) a0[k] = z;
    for (int k = i; k < 64000; k += st) a1[k] = z;
}

// ===========================================================================
// Fused transposed placement: Xt[rowOff+f][r] = H[chain(r)][f] (fp16)
// ===========================================================================
__device__ __forceinline__ void trans_blk(float (*tile)[33],
                                          __half* __restrict__ Bh, int ld,
                                          const float* __restrict__ H, int rows,
                                          const int* __restrict__ s1,
                                          const int* __restrict__ s2, int rowOff, int blk) {
    int tid = threadIdx.x;
    int r0 = blk * 32;
#pragma unroll
    for (int t = 0; t < 4; t++) {
        int g = tid + t * 256;
        int r = g >> 5;
        int c4 = g & 31;
        int sr = r0 + r;
        float4 v = make_float4(0.f, 0.f, 0.f, 0.f);
        if (sr < rows) {
            int s = sr;
            if (s2) s = s2[s];
            if (s1) s = s1[s];
            v = *reinterpret_cast<const float4*>(H + (size_t)s * DIM + c4 * 4);
        }
        tile[c4 * 4 + 0][r] = v.x;
        tile[c4 * 4 + 1][r] = v.y;
        tile[c4 * 4 + 2][r] = v.z;
        tile[c4 * 4 + 3][r] = v.w;
    }
    __syncthreads();
    int f = tid >> 1;
    int half = tid & 1;
#pragma unroll
    for (int m4 = 0; m4 < 4; m4++) {
        int lc = half * 16 + m4 * 4;
        int col = r0 + lc;
        if (col < rows) {
            uint2 h;
            h.x = pkh2(__float2half_rn(tile[f][lc]), __float2half_rn(tile[f][lc + 1]));
            h.y = pkh2(__float2half_rn(tile[f][lc + 2]), __float2half_rn(tile[f][lc + 3]));
            *reinterpret_cast<uint2*>(Bh + (size_t)(rowOff + f) * ld + col) = h;
        }
    }
}

__global__ __launch_bounds__(256) void k_trans_all(
    __half* Bh0p, __half* Bh1p, __half* Bh2p,
    const float* h0, const float* h1, const float* h2,
    const int* idx0, const int* idx1) {
    __shared__ float tile[128][33];
    int b = blockIdx.x;
    if (b < 250)      trans_blk(tile, Bh0p, N0, h0, N0, nullptr, nullptr, 0, b);
    else if (b < 375) trans_blk(tile, Bh1p, N1, h0, N1, idx0, nullptr, 0, b - 250);
    else if (b < 500) trans_blk(tile, Bh1p, N1, h1, N1, nullptr, nullptr, 128, b - 375);
    else if (b < 563) trans_blk(tile, Bh2p, N2, h0, N2, idx0, idx1, 0, b - 500);
    else if (b < 626) trans_blk(tile, Bh2p, N2, h1, N2, idx1, nullptr, 128, b - 563);
    else              trans_blk(tile, Bh2p, N2, h2, N2, nullptr, nullptr, 256, b - 626);
}

// ===========================================================================
// Fused scattered placement (up path), fp16
// ===========================================================================
__device__ __forceinline__ void scat_row(__half* __restrict__ Bh, int ld,
                                         const float* __restrict__ H,
                                         const int* __restrict__ d1,
                                         const int* __restrict__ d2, int rowOff,
                                         int r, int f) {
    float v = H[(size_t)r * DIM + f];
    int dr = r;
    if (d2) dr = d2[dr];
    if (d1) dr = d1[dr];
    Bh[(size_t)(rowOff + f) * ld + dr] = __float2half_rn(v);
}

__global__ __launch_bounds__(256) void k_scatter_all(
    __half* Bh0p, __half* Bh1p,
    const float* h1, const float* h2, const int* idx0, const int* idx1) {
    int b = blockIdx.x;
    int f = threadIdx.x & 127;
    int rh = threadIdx.x >> 7;
    if (b < 2000)      scat_row(Bh0p, N0, h1, idx0, nullptr, 128, b * 2 + rh, f);
    else if (b < 3000) scat_row(Bh0p, N0, h2, idx0, idx1, 256, (b - 2000) * 2 + rh, f);
    else               scat_row(Bh1p, N1, h2, idx1, nullptr, 256, (b - 3000) * 2 + rh, f);
}

// ===========================================================================
// fp16 1-term mma.sync GEMM with FUSED in-kernel A conversion.
// A arrives fp32 via cp.async (8KB/stage); block-level convert (x ASCALE) into
// one shared fp16 A buffer (ldsm swizzle), then ldmatrix+HMMA as before.
// Stage: Araw fp32 8K | Bh fp16 8K = 16384 B x 4 stages + AFP16 4K = 69632 B.
// Grid: 660 CTAs single launch, 2 CTAs/SM.
// ===========================================================================
#define OFF_ARAW 0
#define OFF_BH 8192
#define STAGE_BYTES 16384
#define OFF_AFP16 65536
#define SMEM_MMA 69632

__device__ __forceinline__ void issue_stage(
    uint32_t stg, const float* __restrict__ A, const __half* __restrict__ Bh,
    int rowBase, int nBase, int M, int ld, int gk0, int Klim, int tid) {
    // A fp32: 64 rows x 128B (8 chunks of 16B), flat layout
#pragma unroll
    for (int i = 0; i < 2; i++) {
        int t = tid + i * 256;            // 0..511
        int row = t >> 3, c16 = t & 7;
        int gk = gk0 + c16 * 4;
        const float* src = A + (size_t)(rowBase + row) * ld + gk;
        uint32_t d = stg + OFF_ARAW + row * 128 + c16 * 16;
        int p = (rowBase + row < M && gk < Klim) ? 16 : 0;
        cpa16(d, src, p);
    }
    // B fp16: 128 rows x 4 chunks of 16B, xor-swizzled for ldsm
#pragma unroll
    for (int i = 0; i < 2; i++) {
        int t = tid + i * 256;
        int row = t >> 2, c = t & 3;
        int gk = gk0 + c * 8;
        size_t so = (size_t)(nBase + row) * ld + gk;
        uint32_t d = stg + OFF_BH + row * 64 + ((c ^ ((row >> 1) & 3)) << 4);
        int p = (gk < Klim) ? 16 : 0;
        cpa16(d, Bh + so, p);
    }
}

__global__ __launch_bounds__(256, 2)
void k_mma(const float* __restrict__ A0, const float* __restrict__ A1,
           const float* __restrict__ A2,
           const __half* __restrict__ Bh0p, const __half* __restrict__ Bh1p,
           const __half* __restrict__ Bh2p,
           float* __restrict__ Y0, float* __restrict__ Y1, float* __restrict__ Y2) {
    extern __shared__ char sm[];
    int tid = threadIdx.x;
    int lane = tid & 31;
    int wid = tid >> 5;
    int bx = blockIdx.x;

    const float* A;
    const __half* Bh;
    float* Y;
    int M, ld, mt, nt, nIter, Klim;
    if (bx < 375) {
        mt = bx / 3; nt = bx % 3;
        A = A0; Bh = Bh0p; Y = Y0;
        M = N0; ld = N0; nIter = 250; Klim = N0;
    } else if (bx < 564) {
        int t = bx - 375;
        mt = t / 3; nt = t % 3;
        A = A1; Bh = Bh1p; Y = Y1;
        M = N1; ld = N1; nIter = 125; Klim = N1;
    } else {
        int t = bx - 564;
        mt = t / 3; nt = t % 3;
        A = A2; Bh = Bh2p; Y = Y2;
        M = N2; ld = N2; nIter = 63; Klim = N2;
    }
    int rowBase = mt * 64;
    int nBase = nt * 128;

    uint32_t sbase = smem_to_u32(sm);
    int wm = wid & 1;    // 2 m-warps x 32 rows
    int wn = wid >> 1;   // 4 n-warps x 32 cols

    // Convert-thread geometry: row = tid>>2 (0..63), c = tid&3 (8 floats each)
    int cvRow = tid >> 2;
    int cvC = tid & 3;
    uint32_t cvSrc = OFF_ARAW + cvRow * 128 + cvC * 32;
    uint32_t cvDst = OFF_AFP16 + cvRow * 64 + ((cvC ^ ((cvRow >> 1) & 3)) << 4);

    // ldmatrix geometry
    int rA = lane & 15;
    int cA = lane >> 4;
    int rBl = (lane & 7) + ((lane >> 4) & 1) * 8;
    int cB = (lane >> 3) & 1;
    uint32_t arow[2], aswz[2], brow[2], bswz[2];
#pragma unroll
    for (int mi = 0; mi < 2; mi++) {
        int r = wm * 32 + mi * 16 + rA;
        arow[mi] = (uint32_t)r * 64;
        aswz[mi] = (r >> 1) & 3;
    }
#pragma unroll
    for (int nb = 0; nb < 2; nb++) {
        int r = wn * 32 + nb * 16 + rBl;
        brow[nb] = (uint32_t)r * 64;
        bswz[nb] = (r >> 1) & 3;
    }

    float acc[2][4][4];
#pragma unroll
    for (int mi = 0; mi < 2; mi++)
#pragma unroll
        for (int ni = 0; ni < 4; ni++)
#pragma unroll
            for (int c = 0; c < 4; c++) acc[mi][ni][c] = 0.f;

#pragma unroll
    for (int s = 0; s < 3; s++) {
        issue_stage(sbase + s * STAGE_BYTES, A, Bh, rowBase, nBase, M, ld,
                    s * 32, Klim, tid);
        CP_COMMIT();
    }

    for (int it = 0; it < nIter; it++) {
        CP_WAIT2();
        __syncthreads();
        if (it + 3 < nIter)
            issue_stage(sbase + ((it + 3) & 3) * STAGE_BYTES, A, Bh,
                        rowBase, nBase, M, ld, (it + 3) * 32, Klim, tid);
        CP_COMMIT();

        uint32_t stg = sbase + (it & 3) * STAGE_BYTES;

        // --- Block-level A convert: fp32 (flat) -> fp16 scaled (ldsm swizzle) ---
        {
            const char* smc = sm + (it & 3) * STAGE_BYTES;
            float4 a0 = *reinterpret_cast<const float4*>(smc + cvSrc);
            float4 a1 = *reinterpret_cast<const float4*>(smc + cvSrc + 16);
            uint4 h;
            h.x = pkh2(__float2half_rn(a0.x * ASCALE), __float2half_rn(a0.y * ASCALE));
            h.y = pkh2(__float2half_rn(a0.z * ASCALE), __float2half_rn(a0.w * ASCALE));
            h.z = pkh2(__float2half_rn(a1.x * ASCALE), __float2half_rn(a1.y * ASCALE));
            h.w = pkh2(__float2half_rn(a1.z * ASCALE), __float2half_rn(a1.w * ASCALE));
            *reinterpret_cast<uint4*>(sm + cvDst) = h;
        }
        __syncthreads();

#pragma unroll
        for (int k16 = 0; k16 < 2; k16++) {
            uint32_t ah[2][4], bh[2][4];
#pragma unroll
            for (int mi = 0; mi < 2; mi++) {
                uint32_t off = arow[mi] + ((((uint32_t)(k16 * 2 + cA)) ^ aswz[mi]) << 4);
                ldsm4(ah[mi], sbase + OFF_AFP16 + off);
            }
#pragma unroll
            for (int nb = 0; nb < 2; nb++) {
                uint32_t off = brow[nb] + ((((uint32_t)(k16 * 2 + cB)) ^ bswz[nb]) << 4);
                ldsm4(bh[nb], stg + OFF_BH + off);
            }
#pragma unroll
            for (int mi = 0; mi < 2; mi++)
#pragma unroll
                for (int nb = 0; nb < 2; nb++) {
                    mma16816(acc[mi][2 * nb], ah[mi], &bh[nb][0]);
                    mma16816(acc[mi][2 * nb + 1], ah[mi], &bh[nb][2]);
                }
        }
    }

    int colB = nBase + wn * 32 + (lane & 3) * 2;
#pragma unroll
    for (int mi = 0; mi < 2; mi++)
#pragma unroll
        for (int h = 0; h < 2; h++) {
            int row = rowBase + wm * 32 + mi * 16 + (lane >> 2) + h * 8;
            if (row < M) {
                float* yp = Y + (size_t)row * XW + colB;
#pragma unroll
                for (int ni = 0; ni < 4; ni++)
                    *reinterpret_cast<float2*>(yp + ni * 8) =
                        make_float2(acc[mi][ni][2 * h], acc[mi][ni][2 * h + 1]);
            }
        }
}

// ===========================================================================
// Fused fp32 epilogue; Y is scaled by ASCALE -> unscale on load.
// ===========================================================================
__global__ __launch_bounds__(256) void k_epi(const float* __restrict__ Y0a,
                                             const float* __restrict__ Y1a,
                                             const float* __restrict__ Y2a,
                                             const float* __restrict__ Wall,
                                             const float* __restrict__ ball,
                                             float* __restrict__ outAll) {
    __shared__ float As[16][132];
    __shared__ float Bs[16][128];
    int tid = threadIdx.x;
    int tx = tid & 15;
    int ty = tid >> 4;
    int bx = blockIdx.x;

    const float* Y;
    float* out;
    int M, ilev, mt;
    if (bx < 63) {
        Y = Y0a; out = outAll; M = N0; ilev = 0; mt = bx;
    } else if (bx < 95) {
        Y = Y1a; out = outAll + (size_t)N0 * DIM; M = N1; ilev = 1; mt = bx - 63;
    } else {
        Y = Y2a; out = outAll + (size_t)(N0 + N1) * DIM; M = N2; ilev = 2; mt = bx - 95;
    }
    int rowBase = mt * 128;

    float sum[8][8];
#pragma unroll
    for (int i = 0; i < 8; i++)
#pragma unroll
        for (int j = 0; j < 8; j++) sum[i][j] = 0.f;

    for (int jb = 0; jb < 3; jb++) {
        const float* W = Wall + (size_t)(ilev * 3 + jb) * DIM * DIM;
        float acc[8][8];
#pragma unroll
        for (int i = 0; i < 8; i++)
#pragma unroll
            for (int j = 0; j < 8; j++) acc[i][j] = 0.f;

        for (int k0 = 0; k0 < DIM; k0 += 16) {
#pragma unroll
            for (int l = 0; l < 2; l++) {
                int s = tid + l * 256;
                int r = s >> 2;
                int kq = (s & 3) * 4;
                int grow = rowBase + r;
                float4 v = make_float4(0.f, 0.f, 0.f, 0.f);
                if (grow < M) {
                    v = *reinterpret_cast<const float4*>(Y + (size_t)grow * XW + jb * DIM + k0 + kq);
                    v.x *= AINV; v.y *= AINV; v.z *= AINV; v.w *= AINV;
                }
                As[kq + 0][r] = v.x;
                As[kq + 1][r] = v.y;
                As[kq + 2][r] = v.z;
                As[kq + 3][r] = v.w;
            }
#pragma unroll
            for (int l = 0; l < 2; l++) {
                int s = tid + l * 256;
                int kr = s >> 5;
                int c4 = (s & 31) * 4;
                *reinterpret_cast<float4*>(&Bs[kr][c4]) =
                    *reinterpret_cast<const float4*>(W + (size_t)(k0 + kr) * DIM + c4);
            }
            __syncthreads();
#pragma unroll
            for (int kk = 0; kk < 16; kk++) {
                float a[8], b[8];
                *reinterpret_cast<float4*>(a) = *reinterpret_cast<const float4*>(&As[kk][ty * 8]);
                *reinterpret_cast<float4*>(a + 4) = *reinterpret_cast<const float4*>(&As[kk][ty * 8 + 4]);
                *reinterpret_cast<float4*>(b) = *reinterpret_cast<const float4*>(&Bs[kk][tx * 8]);
                *reinterpret_cast<float4*>(b + 4) = *reinterpret_cast<const float4*>(&Bs[kk][tx * 8 + 4]);
#pragma unroll
                for (int i = 0; i < 8; i++)
#pragma unroll
                    for (int j = 0; j < 8; j++) acc[i][j] += a[i] * b[j];
            }
            __syncthreads();
        }
        const float* bvec = ball + (size_t)(ilev * 3 + jb) * DIM;
#pragma unroll
        for (int j = 0; j < 8; j++) {
            float bb = bvec[tx * 8 + j];
#pragma unroll
            for (int i = 0; i < 8; i++) sum[i][j] += fmaxf(acc[i][j] + bb, 0.f);
        }
    }

#pragma unroll
    for (int i = 0; i < 8; i++) {
        int grow = rowBase + ty * 8 + i;
        if (grow < M) {
            float* op = out + (size_t)grow * DIM + tx * 8;
            *reinterpret_cast<float4*>(op) = make_float4(sum[i][0], sum[i][1], sum[i][2], sum[i][3]);
            *reinterpret_cast<float4*>(op + 4) = make_float4(sum[i][4], sum[i][5], sum[i][6], sum[i][7]);
        }
    }
}

// ===========================================================================
extern "C" void kernel_launch(void* const* d_in, const int* in_sizes, int n_in,
                              void* d_out, int out_size) {
    const float* adj0 = (const float*)d_in[0];
    const float* adj1 = (const float*)d_in[1];
    const float* adj2 = (const float*)d_in[2];
    const float* h0 = (const float*)d_in[3];
    const float* h1 = (const float*)d_in[4];
    const float* h2 = (const float*)d_in[5];
    const int* idx0 = (const int*)d_in[6];
    const int* idx1 = (const int*)d_in[7];
    const float* Ws = (const float*)d_in[8];
    const float* bs = (const float*)d_in[9];
    float* out = (float*)d_out;

    __half *Bh0, *Bh1, *Bh2;
    float *Y0, *Y1, *Y2;
    cudaGetSymbolAddress((void**)&Bh0, g_Bh0);
    cudaGetSymbolAddress((void**)&Bh1, g_Bh1);
    cudaGetSymbolAddress((void**)&Bh2, g_Bh2);
    cudaGetSymbolAddress((void**)&Y0, g_Y0);
    cudaGetSymbolAddress((void**)&Y1, g_Y1);
    cudaGetSymbolAddress((void**)&Y2, g_Y2);

    cudaFuncSetAttribute(k_mma, cudaFuncAttributeMaxDynamicSharedMemorySize, SMEM_MMA);

    // 1. Zero scatter-target B regions
    k_zero_all<<<640, 256>>>((float4*)(Bh0 + (size_t)128 * N0),
                             (float4*)(Bh1 + (size_t)256 * N1));

    // 2. Build Xt fp16
    k_trans_all<<<689, 256>>>(Bh0, Bh1, Bh2, h0, h1, h2, idx0, idx1);
    k_scatter_all<<<4000, 256>>>(Bh0, Bh1, h1, h2, idx0, idx1);

    // 3. Y_i = ASCALE * adj_i @ X_i — fp16 GEMM with fused A conversion
    k_mma<<<660, 256, SMEM_MMA>>>(adj0, adj1, adj2, Bh0, Bh1, Bh2, Y0, Y1, Y2);

    // 4. Fused epilogue (unscales Y)
    k_epi<<<111, 256>>>(Y0, Y1, Y2, Ws, bs, out);
}

// round 15
// speedup vs baseline: 1.0354x; 1.0188x over previous
#include <cuda_runtime.h>
#include <cuda_fp16.h>
#include <cstdint>

#define N0 8000
#define N1 4000
#define N2 2000
#define DIM 128
#define XW 384
#define ASCALE 2048.0f
#define AINV (1.0f / 2048.0f)

// adj fp16 plane (scaled by ASCALE)
__device__ __half g_Ah0[(size_t)N0 * N0];
__device__ __half g_Ah1[(size_t)N1 * N1];
__device__ __half g_Ah2[(size_t)N2 * N2];
// Xt = X^T [384][N_i], fp16
__device__ __half g_Bh0[XW * N0];
__device__ __half g_Bh1[XW * N1];
__device__ __half g_Bh2[XW * N2];
// fp32 Y = ASCALE * (adj @ X)
__device__ float g_Y0[N0 * XW];
__device__ float g_Y1[N1 * XW];
__device__ float g_Y2[N2 * XW];

// ===========================================================================
// helpers
// ===========================================================================
__device__ __forceinline__ uint32_t smem_to_u32(const void* p) {
    uint32_t a;
    asm("{ .reg .u64 t; cvta.to.shared.u64 t, %1; cvt.u32.u64 %0, t; }" : "=r"(a) : "l"(p));
    return a;
}
__device__ __forceinline__ void ldsm4(uint32_t* r, uint32_t addr) {
    asm volatile("ldmatrix.sync.aligned.m8n8.x4.shared.b16 {%0,%1,%2,%3}, [%4];"
                 : "=r"(r[0]), "=r"(r[1]), "=r"(r[2]), "=r"(r[3]) : "r"(addr));
}
__device__ __forceinline__ void mma16816(float* c, const uint32_t* a, const uint32_t* b) {
    asm volatile(
        "mma.sync.aligned.m16n8k16.row.col.f32.f16.f16.f32 "
        "{%0,%1,%2,%3}, {%4,%5,%6,%7}, {%8,%9}, {%0,%1,%2,%3};"
        : "+f"(c[0]), "+f"(c[1]), "+f"(c[2]), "+f"(c[3])
        : "r"(a[0]), "r"(a[1]), "r"(a[2]), "r"(a[3]), "r"(b[0]), "r"(b[1]));
}
__device__ __forceinline__ void cpa16(uint32_t d, const void* s, int sz) {
    asm volatile("cp.async.cg.shared.global [%0], [%1], 16, %2;"
                 :: "r"(d), "l"(s), "r"(sz) : "memory");
}
#define CP_COMMIT() asm volatile("cp.async.commit_group;" ::: "memory")
#define CP_WAIT2() asm volatile("cp.async.wait_group 2;" ::: "memory")

__device__ __forceinline__ uint32_t pkh2(__half x, __half y) {
    __half2 t;
    t.x = x; t.y = y;
    return reinterpret_cast<uint32_t&>(t);
}

// ===========================================================================
// Prepass: adj -> fp16 plane, scaled by ASCALE
// ===========================================================================
__global__ void k_cvt(const float4* __restrict__ in, uint2* __restrict__ hi, int n4) {
    int i = blockIdx.x * blockDim.x + threadIdx.x;
    int stride = gridDim.x * blockDim.x;
    for (; i < n4; i += stride) {
        float4 v = in[i];
        uint2 h;
        h.x = pkh2(__float2half_rn(v.x * ASCALE), __float2half_rn(v.y * ASCALE));
        h.y = pkh2(__float2half_rn(v.z * ASCALE), __float2half_rn(v.w * ASCALE));
        hi[i] = h;
    }
}

// ===========================================================================
// Zero of scatter-target B regions
// ===========================================================================
__global__ void k_zero_all(float4* __restrict__ a0, float4* __restrict__ a1) {
    int i = blockIdx.x * blockDim.x + threadIdx.x;
    int st = gridDim.x * blockDim.x;
    float4 z = make_float4(0.f, 0.f, 0.f, 0.f);
    for (int k = i; k < 256000; k += st) a0[k] = z;
    for (int k = i; k < 64000; k += st) a1[k] = z;
}

// ===========================================================================
// Fused transposed placement: Xt[rowOff+f][r] = H[chain(r)][f] (fp16)
// ===========================================================================
__device__ __forceinline__ void trans_blk(float (*tile)[33],
                                          __half* __restrict__ Bh, int ld,
                                          const float* __restrict__ H, int rows,
                                          const int* __restrict__ s1,
                                          const int* __restrict__ s2, int rowOff, int blk) {
    int tid = threadIdx.x;
    int r0 = blk * 32;
#pragma unroll
    for (int t = 0; t < 4; t++) {
        int g = tid + t * 256;
        int r = g >> 5;
        int c4 = g & 31;
        int sr = r0 + r;
        float4 v = make_float4(0.f, 0.f, 0.f, 0.f);
        if (sr < rows) {
            int s = sr;
            if (s2) s = s2[s];
            if (s1) s = s1[s];
            v = *reinterpret_cast<const float4*>(H + (size_t)s * DIM + c4 * 4);
        }
        tile[c4 * 4 + 0][r] = v.x;
        tile[c4 * 4 + 1][r] = v.y;
        tile[c4 * 4 + 2][r] = v.z;
        tile[c4 * 4 + 3][r] = v.w;
    }
    __syncthreads();
    int f = tid >> 1;
    int half = tid & 1;
#pragma unroll
    for (int m4 = 0; m4 < 4; m4++) {
        int lc = half * 16 + m4 * 4;
        int col = r0 + lc;
        if (col < rows) {
            uint2 h;
            h.x = pkh2(__float2half_rn(tile[f][lc]), __float2half_rn(tile[f][lc + 1]));
            h.y = pkh2(__float2half_rn(tile[f][lc + 2]), __float2half_rn(tile[f][lc + 3]));
            *reinterpret_cast<uint2*>(Bh + (size_t)(rowOff + f) * ld + col) = h;
        }
    }
}

__global__ __launch_bounds__(256) void k_trans_all(
    __half* Bh0p, __half* Bh1p, __half* Bh2p,
    const float* h0, const float* h1, const float* h2,
    const int* idx0, const int* idx1) {
    __shared__ float tile[128][33];
    int b = blockIdx.x;
    if (b < 250)      trans_blk(tile, Bh0p, N0, h0, N0, nullptr, nullptr, 0, b);
    else if (b < 375) trans_blk(tile, Bh1p, N1, h0, N1, idx0, nullptr, 0, b - 250);
    else if (b < 500) trans_blk(tile, Bh1p, N1, h1, N1, nullptr, nullptr, 128, b - 375);
    else if (b < 563) trans_blk(tile, Bh2p, N2, h0, N2, idx0, idx1, 0, b - 500);
    else if (b < 626) trans_blk(tile, Bh2p, N2, h1, N2, idx1, nullptr, 128, b - 563);
    else              trans_blk(tile, Bh2p, N2, h2, N2, nullptr, nullptr, 256, b - 626);
}

// ===========================================================================
// Fused scattered placement (up path), fp16
// ===========================================================================
__device__ __forceinline__ void scat_row(__half* __restrict__ Bh, int ld,
                                         const float* __restrict__ H,
                                         const int* __restrict__ d1,
                                         const int* __restrict__ d2, int rowOff,
                                         int r, int f) {
    float v = H[(size_t)r * DIM + f];
    int dr = r;
    if (d2) dr = d2[dr];
    if (d1) dr = d1[dr];
    Bh[(size_t)(rowOff + f) * ld + dr] = __float2half_rn(v);
}

__global__ __launch_bounds__(256) void k_scatter_all(
    __half* Bh0p, __half* Bh1p,
    const float* h1, const float* h2, const int* idx0, const int* idx1) {
    int b = blockIdx.x;
    int f = threadIdx.x & 127;
    int rh = threadIdx.x >> 7;
    if (b < 2000)      scat_row(Bh0p, N0, h1, idx0, nullptr, 128, b * 2 + rh, f);
    else if (b < 3000) scat_row(Bh0p, N0, h2, idx0, idx1, 256, (b - 2000) * 2 + rh, f);
    else               scat_row(Bh1p, N1, h2, idx1, nullptr, 256, (b - 3000) * 2 + rh, f);
}

// ===========================================================================
// fp16 1-term mma.sync GEMM — M=64 x N=192 tiles, 4 stages x 16KB, 2 CTAs/SM.
// Wave-exact sub-grids via bxOff: L0 [0,250), L1 [250,376), L2 [376,440).
// ===========================================================================
#define OFF_AH 0
#define OFF_BH 4096
#define STAGE_BYTES 16384
#define SMEM_MMA (4 * STAGE_BYTES)   // 65536

__device__ __forceinline__ void issue_stage(
    uint32_t stg, const __half* __restrict__ Ah, const __half* __restrict__ Bh,
    int rowBase, int nBase, int M, int ld, int gk0, int Klim, int tid) {
    // A: 64 rows x 4 chunks of 16B
    {
        int row = tid >> 2, c = tid & 3;
        int gk = gk0 + c * 8;
        size_t so = (size_t)(rowBase + row) * ld + gk;
        uint32_t d = stg + row * 64 + ((c ^ ((row >> 1) & 3)) << 4);
        int p = (rowBase + row < M && gk < Klim) ? 16 : 0;
        cpa16(d + OFF_AH, Ah + so, p);
    }
    // B: 192 rows x 4 chunks of 16B
#pragma unroll
    for (int i = 0; i < 3; i++) {
        int t = tid + i * 256;
        int row = t >> 2, c = t & 3;
        int gk = gk0 + c * 8;
        size_t so = (size_t)(nBase + row) * ld + gk;
        uint32_t d = stg + row * 64 + ((c ^ ((row >> 1) & 3)) << 4);
        int p = (gk < Klim) ? 16 : 0;
        cpa16(d + OFF_BH, Bh + so, p);
    }
}

__global__ __launch_bounds__(256, 2)
void k_mma(const __half* __restrict__ Ah0p, const __half* __restrict__ Ah1p,
           const __half* __restrict__ Ah2p,
           const __half* __restrict__ Bh0p, const __half* __restrict__ Bh1p,
           const __half* __restrict__ Bh2p,
           float* __restrict__ Y0, float* __restrict__ Y1, float* __restrict__ Y2,
           int bxOff) {
    extern __shared__ char sm[];
    int tid = threadIdx.x;
    int lane = tid & 31;
    int wid = tid >> 5;
    int bx = blockIdx.x + bxOff;

    const __half *Ah, *Bh;
    float* Y;
    int M, ld, mt, nt, nIter, Klim;
    if (bx < 250) {
        mt = bx >> 1; nt = bx & 1;
        Ah = Ah0p; Bh = Bh0p; Y = Y0;
        M = N0; ld = N0; nIter = 250; Klim = N0;
    } else if (bx < 376) {
        int t = bx - 250;
        mt = t >> 1; nt = t & 1;
        Ah = Ah1p; Bh = Bh1p; Y = Y1;
        M = N1; ld = N1; nIter = 125; Klim = N1;
    } else {
        int t = bx - 376;
        mt = t >> 1; nt = t & 1;
        Ah = Ah2p; Bh = Bh2p; Y = Y2;
        M = N2; ld = N2; nIter = 63; Klim = N2;
    }
    int rowBase = mt * 64;
    int nBase = nt * 192;

    uint32_t sbase = smem_to_u32(sm);
    int wm = wid & 1;    // 2 m-warps x 32 rows
    int wn = wid >> 1;   // 4 n-warps x 48 cols

    // ldmatrix geometry
    int rA = lane & 15;
    int cA = lane >> 4;
    int rBl = (lane & 7) + ((lane >> 4) & 1) * 8;
    int cB = (lane >> 3) & 1;
    uint32_t arow[2], aswz[2], brow[3], bswz[3];
#pragma unroll
    for (int mi = 0; mi < 2; mi++) {
        int r = wm * 32 + mi * 16 + rA;
        arow[mi] = (uint32_t)r * 64;
        aswz[mi] = (r >> 1) & 3;
    }
#pragma unroll
    for (int nb = 0; nb < 3; nb++) {
        int r = wn * 48 + nb * 16 + rBl;
        brow[nb] = (uint32_t)r * 64;
        bswz[nb] = (r >> 1) & 3;
    }

    float acc[2][6][4];
#pragma unroll
    for (int mi = 0; mi < 2; mi++)
#pragma unroll
        for (int ni = 0; ni < 6; ni++)
#pragma unroll
            for (int c = 0; c < 4; c++) acc[mi][ni][c] = 0.f;

#pragma unroll
    for (int s = 0; s < 3; s++) {
        issue_stage(sbase + s * STAGE_BYTES, Ah, Bh, rowBase, nBase, M, ld,
                    s * 32, Klim, tid);
        CP_COMMIT();
    }

    for (int it = 0; it < nIter; it++) {
        CP_WAIT2();
        __syncthreads();
        if (it + 3 < nIter)
            issue_stage(sbase + ((it + 3) & 3) * STAGE_BYTES, Ah, Bh,
                        rowBase, nBase, M, ld, (it + 3) * 32, Klim, tid);
        CP_COMMIT();

        uint32_t stg = sbase + (it & 3) * STAGE_BYTES;
#pragma unroll
        for (int k16 = 0; k16 < 2; k16++) {
            uint32_t ah[2][4], bh[3][4];
#pragma unroll
            for (int mi = 0; mi < 2; mi++) {
                uint32_t off = arow[mi] + ((((uint32_t)(k16 * 2 + cA)) ^ aswz[mi]) << 4);
                ldsm4(ah[mi], stg + OFF_AH + off);
            }
#pragma unroll
            for (int nb = 0; nb < 3; nb++) {
                uint32_t off = brow[nb] + ((((uint32_t)(k16 * 2 + cB)) ^ bswz[nb]) << 4);
                ldsm4(bh[nb], stg + OFF_BH + off);
            }
#pragma unroll
            for (int mi = 0; mi < 2; mi++)
#pragma unroll
                for (int nb = 0; nb < 3; nb++) {
                    mma16816(acc[mi][2 * nb], ah[mi], &bh[nb][0]);
                    mma16816(acc[mi][2 * nb + 1], ah[mi], &bh[nb][2]);
                }
        }
    }

    int colB = nBase + wn * 48 + (lane & 3) * 2;
#pragma unroll
    for (int mi = 0; mi < 2; mi++)
#pragma unroll
        for (int h = 0; h < 2; h++) {
            int row = rowBase + wm * 32 + mi * 16 + (lane >> 2) + h * 8;
            if (row < M) {
                float* yp = Y + (size_t)row * XW + colB;
#pragma unroll
                for (int ni = 0; ni < 6; ni++)
                    *reinterpret_cast<float2*>(yp + ni * 8) =
                        make_float2(acc[mi][ni][2 * h], acc[mi][ni][2 * h + 1]);
            }
        }
}

// ===========================================================================
// Fused fp32 epilogue; Y is scaled by ASCALE -> unscale on load.
// ===========================================================================
__global__ __launch_bounds__(256) void k_epi(const float* __restrict__ Y0a,
                                             const float* __restrict__ Y1a,
                                             const float* __restrict__ Y2a,
                                             const float* __restrict__ Wall,
                                             const float* __restrict__ ball,
                                             float* __restrict__ outAll) {
    __shared__ float As[16][132];
    __shared__ float Bs[16][128];
    int tid = threadIdx.x;
    int tx = tid & 15;
    int ty = tid >> 4;
    int bx = blockIdx.x;

    const float* Y;
    float* out;
    int M, ilev, mt;
    if (bx < 63) {
        Y = Y0a; out = outAll; M = N0; ilev = 0; mt = bx;
    } else if (bx < 95) {
        Y = Y1a; out = outAll + (size_t)N0 * DIM; M = N1; ilev = 1; mt = bx - 63;
    } else {
        Y = Y2a; out = outAll + (size_t)(N0 + N1) * DIM; M = N2; ilev = 2; mt = bx - 95;
    }
    int rowBase = mt * 128;

    float sum[8][8];
#pragma unroll
    for (int i = 0; i < 8; i++)
#pragma unroll
        for (int j = 0; j < 8; j++) sum[i][j] = 0.f;

    for (int jb = 0; jb < 3; jb++) {
        const float* W = Wall + (size_t)(ilev * 3 + jb) * DIM * DIM;
        float acc[8][8];
#pragma unroll
        for (int i = 0; i < 8; i++)
#pragma unroll
            for (int j = 0; j < 8; j++) acc[i][j] = 0.f;

        for (int k0 = 0; k0 < DIM; k0 += 16) {
#pragma unroll
            for (int l = 0; l < 2; l++) {
                int s = tid + l * 256;
                int r = s >> 2;
                int kq = (s & 3) * 4;
                int grow = rowBase + r;
                float4 v = make_float4(0.f, 0.f, 0.f, 0.f);
                if (grow < M) {
                    v = *reinterpret_cast<const float4*>(Y + (size_t)grow * XW + jb * DIM + k0 + kq);
                    v.x *= AINV; v.y *= AINV; v.z *= AINV; v.w *= AINV;
                }
                As[kq + 0][r] = v.x;
                As[kq + 1][r] = v.y;
                As[kq + 2][r] = v.z;
                As[kq + 3][r] = v.w;
            }
#pragma unroll
            for (int l = 0; l < 2; l++) {
                int s = tid + l * 256;
                int kr = s >> 5;
                int c4 = (s & 31) * 4;
                *reinterpret_cast<float4*>(&Bs[kr][c4]) =
                    *reinterpret_cast<const float4*>(W + (size_t)(k0 + kr) * DIM + c4);
            }
            __syncthreads();
#pragma unroll
            for (int kk = 0; kk < 16; kk++) {
                float a[8], b[8];
                *reinterpret_cast<float4*>(a) = *reinterpret_cast<const float4*>(&As[kk][ty * 8]);
                *reinterpret_cast<float4*>(a + 4) = *reinterpret_cast<const float4*>(&As[kk][ty * 8 + 4]);
                *reinterpret_cast<float4*>(b) = *reinterpret_cast<const float4*>(&Bs[kk][tx * 8]);
                *reinterpret_cast<float4*>(b + 4) = *reinterpret_cast<const float4*>(&Bs[kk][tx * 8 + 4]);
#pragma unroll
                for (int i = 0; i < 8; i++)
#pragma unroll
                    for (int j = 0; j < 8; j++) acc[i][j] += a[i] * b[j];
            }
            __syncthreads();
        }
        const float* bvec = ball + (size_t)(ilev * 3 + jb) * DIM;
#pragma unroll
        for (int j = 0; j < 8; j++) {
            float bb = bvec[tx * 8 + j];
#pragma unroll
            for (int i = 0; i < 8; i++) sum[i][j] += fmaxf(acc[i][j] + bb, 0.f);
        }
    }

#pragma unroll
    for (int i = 0; i < 8; i++) {
        int grow = rowBase + ty * 8 + i;
        if (grow < M) {
            float* op = out + (size_t)grow * DIM + tx * 8;
            *reinterpret_cast<float4*>(op) = make_float4(sum[i][0], sum[i][1], sum[i][2], sum[i][3]);
            *reinterpret_cast<float4*>(op + 4) = make_float4(sum[i][4], sum[i][5], sum[i][6], sum[i][7]);
        }
    }
}

// ===========================================================================
extern "C" void kernel_launch(void* const* d_in, const int* in_sizes, int n_in,
                              void* d_out, int out_size) {
    const float* adj0 = (const float*)d_in[0];
    const float* adj1 = (const float*)d_in[1];
    const float* adj2 = (const float*)d_in[2];
    const float* h0 = (const float*)d_in[3];
    const float* h1 = (const float*)d_in[4];
    const float* h2 = (const float*)d_in[5];
    const int* idx0 = (const int*)d_in[6];
    const int* idx1 = (const int*)d_in[7];
    const float* Ws = (const float*)d_in[8];
    const float* bs = (const float*)d_in[9];
    float* out = (float*)d_out;

    __half *Ah0, *Ah1, *Ah2, *Bh0, *Bh1, *Bh2;
    float *Y0, *Y1, *Y2;
    cudaGetSymbolAddress((void**)&Ah0, g_Ah0);
    cudaGetSymbolAddress((void**)&Ah1, g_Ah1);
    cudaGetSymbolAddress((void**)&Ah2, g_Ah2);
    cudaGetSymbolAddress((void**)&Bh0, g_Bh0);
    cudaGetSymbolAddress((void**)&Bh1, g_Bh1);
    cudaGetSymbolAddress((void**)&Bh2, g_Bh2);
    cudaGetSymbolAddress((void**)&Y0, g_Y0);
    cudaGetSymbolAddress((void**)&Y1, g_Y1);
    cudaGetSymbolAddress((void**)&Y2, g_Y2);

    cudaFuncSetAttribute(k_mma, cudaFuncAttributeMaxDynamicSharedMemorySize, SMEM_MMA);

    // Stream fork: conversions on s2, B build + mma on main (capture) stream.
    cudaStream_t s2;
    cudaStreamCreate(&s2);
    cudaEvent_t evF, evA, evB, evEnd;
    cudaEventCreateWithFlags(&evF, cudaEventDisableTiming);
    cudaEventCreateWithFlags(&evA, cudaEventDisableTiming);
    cudaEventCreateWithFlags(&evB, cudaEventDisableTiming);
    cudaEventCreateWithFlags(&evEnd, cudaEventDisableTiming);

    cudaEventRecord(evF, 0);
    cudaStreamWaitEvent(s2, evF, 0);

    // s2: adj conversions — small levels first, then the big one
    k_cvt<<<1024, 256, 0, s2>>>((const float4*)adj1, (uint2*)Ah1, N1 * N1 / 4);
    k_cvt<<<512, 256, 0, s2>>>((const float4*)adj2, (uint2*)Ah2, N2 * N2 / 4);
    cudaEventRecord(evA, s2);
    k_cvt<<<2048, 256, 0, s2>>>((const float4*)adj0, (uint2*)Ah0,
                                (int)((size_t)N0 * N0 / 4));
    cudaEventRecord(evB, s2);

    // main: B build (independent of conversions)
    k_zero_all<<<640, 256>>>((float4*)(Bh0 + (size_t)128 * N0),
                             (float4*)(Bh1 + (size_t)256 * N1));
    k_trans_all<<<689, 256>>>(Bh0, Bh1, Bh2, h0, h1, h2, idx0, idx1);
    k_scatter_all<<<4000, 256>>>(Bh0, Bh1, h1, h2, idx0, idx1);

    // mma levels 1+2 (190 CTAs, one wave) — overlaps cvt0 on s2
    cudaStreamWaitEvent(0, evA, 0);
    k_mma<<<190, 256, SMEM_MMA>>>(Ah0, Ah1, Ah2, Bh0, Bh1, Bh2, Y0, Y1, Y2, 250);

    // mma level 0 (250 CTAs, one wave)
    cudaStreamWaitEvent(0, evB, 0);
    k_mma<<<250, 256, SMEM_MMA>>>(Ah0, Ah1, Ah2, Bh0, Bh1, Bh2, Y0, Y1, Y2, 0);

    // epilogue
    k_epi<<<111, 256>>>(Y0, Y1, Y2, Ws, bs, out);

    // join s2
    cudaEventRecord(evEnd, s2);
    cudaStreamWaitEvent(0, evEnd, 0);
}

// round 16
// speedup vs baseline: 1.0858x; 1.0487x over previous
#include <cuda_runtime.h>
#include <cuda_fp16.h>
#include <cstdint>

#define N0 8000
#define N1 4000
#define N2 2000
#define DIM 128
#define XW 384
#define ASCALE 2048.0f
#define AINV (1.0f / 2048.0f)

// adj fp16 plane (scaled by ASCALE)
__device__ __half g_Ah0[(size_t)N0 * N0];
__device__ __half g_Ah1[(size_t)N1 * N1];
__device__ __half g_Ah2[(size_t)N2 * N2];
// Xt = X^T [384][N_i], fp16 (single plane)
__device__ __half g_Bh0[XW * N0];
__device__ __half g_Bh1[XW * N1];
__device__ __half g_Bh2[XW * N2];
// fp32 Y = ASCALE * (adj @ X)
__device__ float g_Y0[N0 * XW];
__device__ float g_Y1[N1 * XW];
__device__ float g_Y2[N2 * XW];

// ===========================================================================
// helpers
// ===========================================================================
__device__ __forceinline__ uint32_t smem_to_u32(const void* p) {
    uint32_t a;
    asm("{ .reg .u64 t; cvta.to.shared.u64 t, %1; cvt.u32.u64 %0, t; }" : "=r"(a) : "l"(p));
    return a;
}
__device__ __forceinline__ void ldsm4(uint32_t* r, uint32_t addr) {
    asm volatile("ldmatrix.sync.aligned.m8n8.x4.shared.b16 {%0,%1,%2,%3}, [%4];"
                 : "=r"(r[0]), "=r"(r[1]), "=r"(r[2]), "=r"(r[3]) : "r"(addr));
}
__device__ __forceinline__ void mma16816(float* c, const uint32_t* a, const uint32_t* b) {
    asm volatile(
        "mma.sync.aligned.m16n8k16.row.col.f32.f16.f16.f32 "
        "{%0,%1,%2,%3}, {%4,%5,%6,%7}, {%8,%9}, {%0,%1,%2,%3};"
        : "+f"(c[0]), "+f"(c[1]), "+f"(c[2]), "+f"(c[3])
        : "r"(a[0]), "r"(a[1]), "r"(a[2]), "r"(a[3]), "r"(b[0]), "r"(b[1]));
}
__device__ __forceinline__ void cpa16(uint32_t d, const void* s, int sz) {
    asm volatile("cp.async.cg.shared.global [%0], [%1], 16, %2;"
                 :: "r"(d), "l"(s), "r"(sz) : "memory");
}
#define CP_COMMIT() asm volatile("cp.async.commit_group;" ::: "memory")
#define CP_WAIT2() asm volatile("cp.async.wait_group 2;" ::: "memory")

__device__ __forceinline__ uint32_t pkh2(__half x, __half y) {
    __half2 t;
    t.x = x; t.y = y;
    return reinterpret_cast<uint32_t&>(t);
}

// ===========================================================================
// Prepass: adj -> fp16 plane, scaled by ASCALE
// ===========================================================================
__global__ void k_cvt(const float4* __restrict__ in, uint2* __restrict__ hi, int n4) {
    int i = blockIdx.x * blockDim.x + threadIdx.x;
    int stride = gridDim.x * blockDim.x;
    for (; i < n4; i += stride) {
        float4 v = in[i];
        uint2 h;
        h.x = pkh2(__float2half_rn(v.x * ASCALE), __float2half_rn(v.y * ASCALE));
        h.y = pkh2(__float2half_rn(v.z * ASCALE), __float2half_rn(v.w * ASCALE));
        hi[i] = h;
    }
}

// ===========================================================================
// Zero of scatter-target B regions
// ===========================================================================
__global__ void k_zero_all(float4* __restrict__ a0, float4* __restrict__ a1) {
    int i = blockIdx.x * blockDim.x + threadIdx.x;
    int st = gridDim.x * blockDim.x;
    float4 z = make_float4(0.f, 0.f, 0.f, 0.f);
    for (int k = i; k < 256000; k += st) a0[k] = z;
    for (int k = i; k < 64000; k += st) a1[k] = z;
}

// ===========================================================================
// Fused transposed placement: Xt[rowOff+f][r] = H[chain(r)][f] (fp16)
// ===========================================================================
__device__ __forceinline__ void trans_blk(float (*tile)[33],
                                          __half* __restrict__ Bh, int ld,
                                          const float* __restrict__ H, int rows,
                                          const int* __restrict__ s1,
                                          const int* __restrict__ s2, int rowOff, int blk) {
    int tid = threadIdx.x;
    int r0 = blk * 32;
#pragma unroll
    for (int t = 0; t < 4; t++) {
        int g = tid + t * 256;
        int r = g >> 5;
        int c4 = g & 31;
        int sr = r0 + r;
        float4 v = make_float4(0.f, 0.f, 0.f, 0.f);
        if (sr < rows) {
            int s = sr;
            if (s2) s = s2[s];
            if (s1) s = s1[s];
            v = *reinterpret_cast<const float4*>(H + (size_t)s * DIM + c4 * 4);
        }
        tile[c4 * 4 + 0][r] = v.x;
        tile[c4 * 4 + 1][r] = v.y;
        tile[c4 * 4 + 2][r] = v.z;
        tile[c4 * 4 + 3][r] = v.w;
    }
    __syncthreads();
    int f = tid >> 1;
    int half = tid & 1;
#pragma unroll
    for (int m4 = 0; m4 < 4; m4++) {
        int lc = half * 16 + m4 * 4;
        int col = r0 + lc;
        if (col < rows) {
            uint2 h;
            h.x = pkh2(__float2half_rn(tile[f][lc]), __float2half_rn(tile[f][lc + 1]));
            h.y = pkh2(__float2half_rn(tile[f][lc + 2]), __float2half_rn(tile[f][lc + 3]));
            *reinterpret_cast<uint2*>(Bh + (size_t)(rowOff + f) * ld + col) = h;
        }
    }
}

__global__ __launch_bounds__(256) void k_trans_all(
    __half* Bh0p, __half* Bh1p, __half* Bh2p,
    const float* h0, const float* h1, const float* h2,
    const int* idx0, const int* idx1) {
    __shared__ float tile[128][33];
    int b = blockIdx.x;
    if (b < 250)      trans_blk(tile, Bh0p, N0, h0, N0, nullptr, nullptr, 0, b);
    else if (b < 375) trans_blk(tile, Bh1p, N1, h0, N1, idx0, nullptr, 0, b - 250);
    else if (b < 500) trans_blk(tile, Bh1p, N1, h1, N1, nullptr, nullptr, 128, b - 375);
    else if (b < 563) trans_blk(tile, Bh2p, N2, h0, N2, idx0, idx1, 0, b - 500);
    else if (b < 626) trans_blk(tile, Bh2p, N2, h1, N2, idx1, nullptr, 128, b - 563);
    else              trans_blk(tile, Bh2p, N2, h2, N2, nullptr, nullptr, 256, b - 626);
}

// ===========================================================================
// Fused scattered placement (up path), fp16
// ===========================================================================
__device__ __forceinline__ void scat_row(__half* __restrict__ Bh, int ld,
                                         const float* __restrict__ H,
                                         const int* __restrict__ d1,
                                         const int* __restrict__ d2, int rowOff,
                                         int r, int f) {
    float v = H[(size_t)r * DIM + f];
    int dr = r;
    if (d2) dr = d2[dr];
    if (d1) dr = d1[dr];
    Bh[(size_t)(rowOff + f) * ld + dr] = __float2half_rn(v);
}

__global__ __launch_bounds__(256) void k_scatter_all(
    __half* Bh0p, __half* Bh1p,
    const float* h1, const float* h2, const int* idx0, const int* idx1) {
    int b = blockIdx.x;
    int f = threadIdx.x & 127;
    int rh = threadIdx.x >> 7;
    if (b < 2000)      scat_row(Bh0p, N0, h1, idx0, nullptr, 128, b * 2 + rh, f);
    else if (b < 3000) scat_row(Bh0p, N0, h2, idx0, idx1, 256, (b - 2000) * 2 + rh, f);
    else               scat_row(Bh1p, N1, h2, idx1, nullptr, 256, (b - 3000) * 2 + rh, f);
}

// ===========================================================================
// fp16 1-term mma.sync GEMM (M=64 x N=128, 4 stages x 12KB, 2 CTAs/SM,
// all-ldmatrix). Y = Ah * Bh. Grid: 660 CTAs single launch. (R12 verbatim)
// ===========================================================================
#define OFF_AH 0
#define OFF_BH 4096
#define STAGE_BYTES 12288
#define SMEM_MMA (4 * STAGE_BYTES)   // 49152

__device__ __forceinline__ void issue_stage(
    uint32_t stg, const __half* __restrict__ Ah, const __half* __restrict__ Bh,
    int rowBase, int nBase, int M, int ld, int gk0, int Klim, int tid) {
    // A: 64 rows x 4 chunks of 16B
    {
        int row = tid >> 2, c = tid & 3;
        int gk = gk0 + c * 8;
        size_t so = (size_t)(rowBase + row) * ld + gk;
        uint32_t d = stg + row * 64 + ((c ^ ((row >> 1) & 3)) << 4);
        int p = (rowBase + row < M && gk < Klim) ? 16 : 0;
        cpa16(d + OFF_AH, Ah + so, p);
    }
    // B: 128 rows x 4 chunks
#pragma unroll
    for (int i = 0; i < 2; i++) {
        int t = tid + i * 256;
        int row = t >> 2, c = t & 3;
        int gk = gk0 + c * 8;
        size_t so = (size_t)(nBase + row) * ld + gk;
        uint32_t d = stg + row * 64 + ((c ^ ((row >> 1) & 3)) << 4);
        int p = (gk < Klim) ? 16 : 0;
        cpa16(d + OFF_BH, Bh + so, p);
    }
}

__global__ __launch_bounds__(256, 2)
void k_mma(const __half* __restrict__ Ah0p, const __half* __restrict__ Ah1p,
           const __half* __restrict__ Ah2p,
           const __half* __restrict__ Bh0p, const __half* __restrict__ Bh1p,
           const __half* __restrict__ Bh2p,
           float* __restrict__ Y0, float* __restrict__ Y1, float* __restrict__ Y2) {
    extern __shared__ char sm[];
    int tid = threadIdx.x;
    int lane = tid & 31;
    int wid = tid >> 5;
    int bx = blockIdx.x;

    const __half *Ah, *Bh;
    float* Y;
    int M, ld, mt, nt, nIter, Klim;
    if (bx < 375) {
        mt = bx / 3; nt = bx % 3;
        Ah = Ah0p; Bh = Bh0p; Y = Y0;
        M = N0; ld = N0; nIter = 250; Klim = N0;
    } else if (bx < 564) {
        int t = bx - 375;
        mt = t / 3; nt = t % 3;
        Ah = Ah1p; Bh = Bh1p; Y = Y1;
        M = N1; ld = N1; nIter = 125; Klim = N1;
    } else {
        int t = bx - 564;
        mt = t / 3; nt = t % 3;
        Ah = Ah2p; Bh = Bh2p; Y = Y2;
        M = N2; ld = N2; nIter = 63; Klim = N2;
    }
    int rowBase = mt * 64;
    int nBase = nt * 128;

    uint32_t sbase = smem_to_u32(sm);
    int wm = wid & 1;    // 2 m-warps x 32 rows
    int wn = wid >> 1;   // 4 n-warps x 32 cols

    // ldmatrix geometry
    int rA = lane & 15;
    int cA = lane >> 4;
    int rBl = (lane & 7) + ((lane >> 4) & 1) * 8;
    int cB = (lane >> 3) & 1;
    uint32_t arow[2], aswz[2], brow[2], bswz[2];
#pragma unroll
    for (int mi = 0; mi < 2; mi++) {
        int r = wm * 32 + mi * 16 + rA;
        arow[mi] = (uint32_t)r * 64;
        aswz[mi] = (r >> 1) & 3;
    }
#pragma unroll
    for (int nb = 0; nb < 2; nb++) {
        int r = wn * 32 + nb * 16 + rBl;
        brow[nb] = (uint32_t)r * 64;
        bswz[nb] = (r >> 1) & 3;
    }

    float acc[2][4][4];
#pragma unroll
    for (int mi = 0; mi < 2; mi++)
#pragma unroll
        for (int ni = 0; ni < 4; ni++)
#pragma unroll
            for (int c = 0; c < 4; c++) acc[mi][ni][c] = 0.f;

#pragma unroll
    for (int s = 0; s < 3; s++) {
        issue_stage(sbase + s * STAGE_BYTES, Ah, Bh, rowBase, nBase, M, ld,
                    s * 32, Klim, tid);
        CP_COMMIT();
    }

    for (int it = 0; it < nIter; it++) {
        CP_WAIT2();
        __syncthreads();
        if (it + 3 < nIter)
            issue_stage(sbase + ((it + 3) & 3) * STAGE_BYTES, Ah, Bh,
                        rowBase, nBase, M, ld, (it + 3) * 32, Klim, tid);
        CP_COMMIT();

        uint32_t stg = sbase + (it & 3) * STAGE_BYTES;
#pragma unroll
        for (int k16 = 0; k16 < 2; k16++) {
            uint32_t ah[2][4], bh[2][4];
#pragma unroll
            for (int mi = 0; mi < 2; mi++) {
                uint32_t off = arow[mi] + ((((uint32_t)(k16 * 2 + cA)) ^ aswz[mi]) << 4);
                ldsm4(ah[mi], stg + OFF_AH + off);
            }
#pragma unroll
            for (int nb = 0; nb < 2; nb++) {
                uint32_t off = brow[nb] + ((((uint32_t)(k16 * 2 + cB)) ^ bswz[nb]) << 4);
                ldsm4(bh[nb], stg + OFF_BH + off);
            }
#pragma unroll
            for (int mi = 0; mi < 2; mi++)
#pragma unroll
                for (int nb = 0; nb < 2; nb++) {
                    mma16816(acc[mi][2 * nb], ah[mi], &bh[nb][0]);
                    mma16816(acc[mi][2 * nb + 1], ah[mi], &bh[nb][2]);
                }
        }
    }

    int colB = nBase + wn * 32 + (lane & 3) * 2;
#pragma unroll
    for (int mi = 0; mi < 2; mi++)
#pragma unroll
        for (int h = 0; h < 2; h++) {
            int row = rowBase + wm * 32 + mi * 16 + (lane >> 2) + h * 8;
            if (row < M) {
                float* yp = Y + (size_t)row * XW + colB;
#pragma unroll
                for (int ni = 0; ni < 4; ni++)
                    *reinterpret_cast<float2*>(yp + ni * 8) =
                        make_float2(acc[mi][ni][2 * h], acc[mi][ni][2 * h + 1]);
            }
        }
}

// ===========================================================================
// Fused fp32 epilogue; Y is scaled by ASCALE -> unscale on load.
// ===========================================================================
__global__ __launch_bounds__(256) void k_epi(const float* __restrict__ Y0a,
                                             const float* __restrict__ Y1a,
                                             const float* __restrict__ Y2a,
                                             const float* __restrict__ Wall,
                                             const float* __restrict__ ball,
                                             float* __restrict__ outAll) {
    __shared__ float As[16][132];
    __shared__ float Bs[16][128];
    int tid = threadIdx.x;
    int tx = tid & 15;
    int ty = tid >> 4;
    int bx = blockIdx.x;

    const float* Y;
    float* out;
    int M, ilev, mt;
    if (bx < 63) {
        Y = Y0a; out = outAll; M = N0; ilev = 0; mt = bx;
    } else if (bx < 95) {
        Y = Y1a; out = outAll + (size_t)N0 * DIM; M = N1; ilev = 1; mt = bx - 63;
    } else {
        Y = Y2a; out = outAll + (size_t)(N0 + N1) * DIM; M = N2; ilev = 2; mt = bx - 95;
    }
    int rowBase = mt * 128;

    float sum[8][8];
#pragma unroll
    for (int i = 0; i < 8; i++)
#pragma unroll
        for (int j = 0; j < 8; j++) sum[i][j] = 0.f;

    for (int jb = 0; jb < 3; jb++) {
        const float* W = Wall + (size_t)(ilev * 3 + jb) * DIM * DIM;
        float acc[8][8];
#pragma unroll
        for (int i = 0; i < 8; i++)
#pragma unroll
            for (int j = 0; j < 8; j++) acc[i][j] = 0.f;

        for (int k0 = 0; k0 < DIM; k0 += 16) {
#pragma unroll
            for (int l = 0; l < 2; l++) {
                int s = tid + l * 256;
                int r = s >> 2;
                int kq = (s & 3) * 4;
                int grow = rowBase + r;
                float4 v = make_float4(0.f, 0.f, 0.f, 0.f);
                if (grow < M) {
                    v = *reinterpret_cast<const float4*>(Y + (size_t)grow * XW + jb * DIM + k0 + kq);
                    v.x *= AINV; v.y *= AINV; v.z *= AINV; v.w *= AINV;
                }
                As[kq + 0][r] = v.x;
                As[kq + 1][r] = v.y;
                As[kq + 2][r] = v.z;
                As[kq + 3][r] = v.w;
            }
#pragma unroll
            for (int l = 0; l < 2; l++) {
                int s = tid + l * 256;
                int kr = s >> 5;
                int c4 = (s & 31) * 4;
                *reinterpret_cast<float4*>(&Bs[kr][c4]) =
                    *reinterpret_cast<const float4*>(W + (size_t)(k0 + kr) * DIM + c4);
            }
            __syncthreads();
#pragma unroll
            for (int kk = 0; kk < 16; kk++) {
                float a[8], b[8];
                *reinterpret_cast<float4*>(a) = *reinterpret_cast<const float4*>(&As[kk][ty * 8]);
                *reinterpret_cast<float4*>(a + 4) = *reinterpret_cast<const float4*>(&As[kk][ty * 8 + 4]);
                *reinterpret_cast<float4*>(b) = *reinterpret_cast<const float4*>(&Bs[kk][tx * 8]);
                *reinterpret_cast<float4*>(b + 4) = *reinterpret_cast<const float4*>(&Bs[kk][tx * 8 + 4]);
#pragma unroll
                for (int i = 0; i < 8; i++)
#pragma unroll
                    for (int j = 0; j < 8; j++) acc[i][j] += a[i] * b[j];
            }
            __syncthreads();
        }
        const float* bvec = ball + (size_t)(ilev * 3 + jb) * DIM;
#pragma unroll
        for (int j = 0; j < 8; j++) {
            float bb = bvec[tx * 8 + j];
#pragma unroll
            for (int i = 0; i < 8; i++) sum[i][j] += fmaxf(acc[i][j] + bb, 0.f);
        }
    }

#pragma unroll
    for (int i = 0; i < 8; i++) {
        int grow = rowBase + ty * 8 + i;
        if (grow < M) {
            float* op = out + (size_t)grow * DIM + tx * 8;
            *reinterpret_cast<float4*>(op) = make_float4(sum[i][0], sum[i][1], sum[i][2], sum[i][3]);
            *reinterpret_cast<float4*>(op + 4) = make_float4(sum[i][4], sum[i][5], sum[i][6], sum[i][7]);
        }
    }
}

// ===========================================================================
extern "C" void kernel_launch(void* const* d_in, const int* in_sizes, int n_in,
                              void* d_out, int out_size) {
    const float* adj0 = (const float*)d_in[0];
    const float* adj1 = (const float*)d_in[1];
    const float* adj2 = (const float*)d_in[2];
    const float* h0 = (const float*)d_in[3];
    const float* h1 = (const float*)d_in[4];
    const float* h2 = (const float*)d_in[5];
    const int* idx0 = (const int*)d_in[6];
    const int* idx1 = (const int*)d_in[7];
    const float* Ws = (const float*)d_in[8];
    const float* bs = (const float*)d_in[9];
    float* out = (float*)d_out;

    __half *Ah0, *Ah1, *Ah2, *Bh0, *Bh1, *Bh2;
    float *Y0, *Y1, *Y2;
    cudaGetSymbolAddress((void**)&Ah0, g_Ah0);
    cudaGetSymbolAddress((void**)&Ah1, g_Ah1);
    cudaGetSymbolAddress((void**)&Ah2, g_Ah2);
    cudaGetSymbolAddress((void**)&Bh0, g_Bh0);
    cudaGetSymbolAddress((void**)&Bh1, g_Bh1);
    cudaGetSymbolAddress((void**)&Bh2, g_Bh2);
    cudaGetSymbolAddress((void**)&Y0, g_Y0);
    cudaGetSymbolAddress((void**)&Y1, g_Y1);
    cudaGetSymbolAddress((void**)&Y2, g_Y2);

    cudaFuncSetAttribute(k_mma, cudaFuncAttributeMaxDynamicSharedMemorySize, SMEM_MMA);

    // Fork: A-conversions on s2; independent B build on main stream.
    cudaStream_t s2;
    cudaStreamCreate(&s2);
    cudaEvent_t evF, evB;
    cudaEventCreateWithFlags(&evF, cudaEventDisableTiming);
    cudaEventCreateWithFlags(&evB, cudaEventDisableTiming);

    cudaEventRecord(evF, 0);
    cudaStreamWaitEvent(s2, evF, 0);

    // s2: adj -> fp16 (scaled); big level first
    k_cvt<<<2048, 256, 0, s2>>>((const float4*)adj0, (uint2*)Ah0,
                                (int)((size_t)N0 * N0 / 4));
    k_cvt<<<1024, 256, 0, s2>>>((const float4*)adj1, (uint2*)Ah1, N1 * N1 / 4);
    k_cvt<<<512, 256, 0, s2>>>((const float4*)adj2, (uint2*)Ah2, N2 * N2 / 4);
    cudaEventRecord(evB, s2);

    // main: B build (independent of conversions; overlaps cvt)
    k_zero_all<<<640, 256>>>((float4*)(Bh0 + (size_t)128 * N0),
                             (float4*)(Bh1 + (size_t)256 * N1));
    k_trans_all<<<689, 256>>>(Bh0, Bh1, Bh2, h0, h1, h2, idx0, idx1);
    k_scatter_all<<<4000, 256>>>(Bh0, Bh1, h1, h2, idx0, idx1);

    // join, then the proven single 660-CTA GEMM
    cudaStreamWaitEvent(0, evB, 0);
    k_mma<<<660, 256, SMEM_MMA>>>(Ah0, Ah1, Ah2, Bh0, Bh1, Bh2, Y0, Y1, Y2);

    // epilogue (unscales Y)
    k_epi<<<111, 256>>>(Y0, Y1, Y2, Ws, bs, out);
}

// round 17
// speedup vs baseline: 1.2403x; 1.1423x over previous
#include <cuda_runtime.h>
#include <cuda_fp16.h>
#include <cstdint>

#define N0 8000
#define N1 4000
#define N2 2000
#define DIM 128
#define XW 384
#define ASCALE 2048.0f
#define AINV (1.0f / 2048.0f)

// adj fp16 plane (scaled by ASCALE)
__device__ __half g_Ah0[(size_t)N0 * N0];
__device__ __half g_Ah1[(size_t)N1 * N1];
__device__ __half g_Ah2[(size_t)N2 * N2];
// Xt = X^T [384][N_i], fp16
__device__ __half g_Bh0[XW * N0];
__device__ __half g_Bh1[XW * N1];
__device__ __half g_Bh2[XW * N2];
// per-j epilogue partials: E[j][row][128], j = 0..2
__device__ float g_E0[3 * N0 * DIM];
__device__ float g_E1[3 * N1 * DIM];
__device__ float g_E2[3 * N2 * DIM];

// ===========================================================================
// helpers
// ===========================================================================
__device__ __forceinline__ uint32_t smem_to_u32(const void* p) {
    uint32_t a;
    asm("{ .reg .u64 t; cvta.to.shared.u64 t, %1; cvt.u32.u64 %0, t; }" : "=r"(a) : "l"(p));
    return a;
}
__device__ __forceinline__ void ldsm4(uint32_t* r, uint32_t addr) {
    asm volatile("ldmatrix.sync.aligned.m8n8.x4.shared.b16 {%0,%1,%2,%3}, [%4];"
                 : "=r"(r[0]), "=r"(r[1]), "=r"(r[2]), "=r"(r[3]) : "r"(addr));
}
__device__ __forceinline__ void ldsm4t(uint32_t* r, uint32_t addr) {
    asm volatile("ldmatrix.sync.aligned.m8n8.x4.trans.shared.b16 {%0,%1,%2,%3}, [%4];"
                 : "=r"(r[0]), "=r"(r[1]), "=r"(r[2]), "=r"(r[3]) : "r"(addr));
}
__device__ __forceinline__ void mma16816(float* c, const uint32_t* a, const uint32_t* b) {
    asm volatile(
        "mma.sync.aligned.m16n8k16.row.col.f32.f16.f16.f32 "
        "{%0,%1,%2,%3}, {%4,%5,%6,%7}, {%8,%9}, {%0,%1,%2,%3};"
        : "+f"(c[0]), "+f"(c[1]), "+f"(c[2]), "+f"(c[3])
        : "r"(a[0]), "r"(a[1]), "r"(a[2]), "r"(a[3]), "r"(b[0]), "r"(b[1]));
}
__device__ __forceinline__ void cpa16(uint32_t d, const void* s, int sz) {
    asm volatile("cp.async.cg.shared.global [%0], [%1], 16, %2;"
                 :: "r"(d), "l"(s), "r"(sz) : "memory");
}
#define CP_COMMIT() asm volatile("cp.async.commit_group;" ::: "memory")
#define CP_WAIT2() asm volatile("cp.async.wait_group 2;" ::: "memory")
#define CP_WAIT0() asm volatile("cp.async.wait_group 0;" ::: "memory")

__device__ __forceinline__ uint32_t pkh2(__half x, __half y) {
    __half2 t;
    t.x = x; t.y = y;
    return reinterpret_cast<uint32_t&>(t);
}
__device__ __forceinline__ uint32_t pkf2(float x, float y) {
    return pkh2(__float2half_rn(x), __float2half_rn(y));
}

// ===========================================================================
// Prepass: adj -> fp16 plane, scaled by ASCALE
// ===========================================================================
__global__ void k_cvt(const float4* __restrict__ in, uint2* __restrict__ hi, int n4) {
    int i = blockIdx.x * blockDim.x + threadIdx.x;
    int stride = gridDim.x * blockDim.x;
    for (; i < n4; i += stride) {
        float4 v = in[i];
        uint2 h;
        h.x = pkf2(v.x * ASCALE, v.y * ASCALE);
        h.y = pkf2(v.z * ASCALE, v.w * ASCALE);
        hi[i] = h;
    }
}

// ===========================================================================
// Zero of scatter-target B regions
// ===========================================================================
__global__ void k_zero_all(float4* __restrict__ a0, float4* __restrict__ a1) {
    int i = blockIdx.x * blockDim.x + threadIdx.x;
    int st = gridDim.x * blockDim.x;
    float4 z = make_float4(0.f, 0.f, 0.f, 0.f);
    for (int k = i; k < 256000; k += st) a0[k] = z;
    for (int k = i; k < 64000; k += st) a1[k] = z;
}

// ===========================================================================
// Fused transposed placement: Xt[rowOff+f][r] = H[chain(r)][f] (fp16)
// ===========================================================================
__device__ __forceinline__ void trans_blk(float (*tile)[33],
                                          __half* __restrict__ Bh, int ld,
                                          const float* __restrict__ H, int rows,
                                          const int* __restrict__ s1,
                                          const int* __restrict__ s2, int rowOff, int blk) {
    int tid = threadIdx.x;
    int r0 = blk * 32;
#pragma unroll
    for (int t = 0; t < 4; t++) {
        int g = tid + t * 256;
        int r = g >> 5;
        int c4 = g & 31;
        int sr = r0 + r;
        float4 v = make_float4(0.f, 0.f, 0.f, 0.f);
        if (sr < rows) {
            int s = sr;
            if (s2) s = s2[s];
            if (s1) s = s1[s];
            v = *reinterpret_cast<const float4*>(H + (size_t)s * DIM + c4 * 4);
        }
        tile[c4 * 4 + 0][r] = v.x;
        tile[c4 * 4 + 1][r] = v.y;
        tile[c4 * 4 + 2][r] = v.z;
        tile[c4 * 4 + 3][r] = v.w;
    }
    __syncthreads();
    int f = tid >> 1;
    int half = tid & 1;
#pragma unroll
    for (int m4 = 0; m4 < 4; m4++) {
        int lc = half * 16 + m4 * 4;
        int col = r0 + lc;
        if (col < rows) {
            uint2 h;
            h.x = pkf2(tile[f][lc], tile[f][lc + 1]);
            h.y = pkf2(tile[f][lc + 2], tile[f][lc + 3]);
            *reinterpret_cast<uint2*>(Bh + (size_t)(rowOff + f) * ld + col) = h;
        }
    }
}

__global__ __launch_bounds__(256) void k_trans_all(
    __half* Bh0p, __half* Bh1p, __half* Bh2p,
    const float* h0, const float* h1, const float* h2,
    const int* idx0, const int* idx1) {
    __shared__ float tile[128][33];
    int b = blockIdx.x;
    if (b < 250)      trans_blk(tile, Bh0p, N0, h0, N0, nullptr, nullptr, 0, b);
    else if (b < 375) trans_blk(tile, Bh1p, N1, h0, N1, idx0, nullptr, 0, b - 250);
    else if (b < 500) trans_blk(tile, Bh1p, N1, h1, N1, nullptr, nullptr, 128, b - 375);
    else if (b < 563) trans_blk(tile, Bh2p, N2, h0, N2, idx0, idx1, 0, b - 500);
    else if (b < 626) trans_blk(tile, Bh2p, N2, h1, N2, idx1, nullptr, 128, b - 563);
    else              trans_blk(tile, Bh2p, N2, h2, N2, nullptr, nullptr, 256, b - 626);
}

// ===========================================================================
// Fused scattered placement (up path), fp16
// ===========================================================================
__device__ __forceinline__ void scat_row(__half* __restrict__ Bh, int ld,
                                         const float* __restrict__ H,
                                         const int* __restrict__ d1,
                                         const int* __restrict__ d2, int rowOff,
                                         int r, int f) {
    float v = H[(size_t)r * DIM + f];
    int dr = r;
    if (d2) dr = d2[dr];
    if (d1) dr = d1[dr];
    Bh[(size_t)(rowOff + f) * ld + dr] = __float2half_rn(v);
}

__global__ __launch_bounds__(256) void k_scatter_all(
    __half* Bh0p, __half* Bh1p,
    const float* h1, const float* h2, const int* idx0, const int* idx1) {
    int b = blockIdx.x;
    int f = threadIdx.x & 127;
    int rh = threadIdx.x >> 7;
    if (b < 2000)      scat_row(Bh0p, N0, h1, idx0, nullptr, 128, b * 2 + rh, f);
    else if (b < 3000) scat_row(Bh0p, N0, h2, idx0, idx1, 256, (b - 2000) * 2 + rh, f);
    else               scat_row(Bh1p, N1, h2, idx1, nullptr, 256, (b - 3000) * 2 + rh, f);
}

// ===========================================================================
// fp16 GEMM + fused epilogue.
// Mainloop: R12 verbatim (M=64 x N=128, 4 stages x 12KB, all-ldmatrix).
// Epilogue: P = fp16(acc*AINV) in smem [0,32K); W[i,nt] fp16 [k][n] in
// [32K,64K); out_term = relu(P @ W + b); written to per-j partial buffer.
// ===========================================================================
#define OFF_AH 0
#define OFF_BH 4096
#define STAGE_BYTES 12288
#define OFF_W 32768
#define SMEM_MMA 65536

__device__ __forceinline__ void issue_stage(
    uint32_t stg, const __half* __restrict__ Ah, const __half* __restrict__ Bh,
    int rowBase, int nBase, int M, int ld, int gk0, int Klim, int tid) {
    {
        int row = tid >> 2, c = tid & 3;
        int gk = gk0 + c * 8;
        size_t so = (size_t)(rowBase + row) * ld + gk;
        uint32_t d = stg + row * 64 + ((c ^ ((row >> 1) & 3)) << 4);
        int p = (rowBase + row < M && gk < Klim) ? 16 : 0;
        cpa16(d + OFF_AH, Ah + so, p);
    }
#pragma unroll
    for (int i = 0; i < 2; i++) {
        int t = tid + i * 256;
        int row = t >> 2, c = t & 3;
        int gk = gk0 + c * 8;
        size_t so = (size_t)(nBase + row) * ld + gk;
        uint32_t d = stg + row * 64 + ((c ^ ((row >> 1) & 3)) << 4);
        int p = (gk < Klim) ? 16 : 0;
        cpa16(d + OFF_BH, Bh + so, p);
    }
}

__global__ __launch_bounds__(256, 2)
void k_mma(const __half* __restrict__ Ah0p, const __half* __restrict__ Ah1p,
           const __half* __restrict__ Ah2p,
           const __half* __restrict__ Bh0p, const __half* __restrict__ Bh1p,
           const __half* __restrict__ Bh2p,
           const float* __restrict__ Wall, const float* __restrict__ ball,
           float* __restrict__ E0, float* __restrict__ E1, float* __restrict__ E2) {
    extern __shared__ char sm[];
    int tid = threadIdx.x;
    int lane = tid & 31;
    int wid = tid >> 5;
    int bx = blockIdx.x;

    const __half *Ah, *Bh;
    float* E;
    int M, ld, mt, nt, nIter, Klim, ilev;
    if (bx < 375) {
        mt = bx / 3; nt = bx % 3;
        Ah = Ah0p; Bh = Bh0p; E = E0;
        M = N0; ld = N0; nIter = 250; Klim = N0; ilev = 0;
    } else if (bx < 564) {
        int t = bx - 375;
        mt = t / 3; nt = t % 3;
        Ah = Ah1p; Bh = Bh1p; E = E1;
        M = N1; ld = N1; nIter = 125; Klim = N1; ilev = 1;
    } else {
        int t = bx - 564;
        mt = t / 3; nt = t % 3;
        Ah = Ah2p; Bh = Bh2p; E = E2;
        M = N2; ld = N2; nIter = 63; Klim = N2; ilev = 2;
    }
    int rowBase = mt * 64;
    int nBase = nt * 128;

    uint32_t sbase = smem_to_u32(sm);
    int wm = wid & 1;
    int wn = wid >> 1;

    // ldmatrix geometry (mainloop)
    int rA = lane & 15;
    int cA = lane >> 4;
    int rBl = (lane & 7) + ((lane >> 4) & 1) * 8;
    int cB = (lane >> 3) & 1;
    uint32_t arow[2], aswz[2], brow[2], bswz[2];
#pragma unroll
    for (int mi = 0; mi < 2; mi++) {
        int r = wm * 32 + mi * 16 + rA;
        arow[mi] = (uint32_t)r * 64;
        aswz[mi] = (r >> 1) & 3;
    }
#pragma unroll
    for (int nb = 0; nb < 2; nb++) {
        int r = wn * 32 + nb * 16 + rBl;
        brow[nb] = (uint32_t)r * 64;
        bswz[nb] = (r >> 1) & 3;
    }

    float acc[2][4][4];
#pragma unroll
    for (int mi = 0; mi < 2; mi++)
#pragma unroll
        for (int ni = 0; ni < 4; ni++)
#pragma unroll
            for (int c = 0; c < 4; c++) acc[mi][ni][c] = 0.f;

#pragma unroll
    for (int s = 0; s < 3; s++) {
        issue_stage(sbase + s * STAGE_BYTES, Ah, Bh, rowBase, nBase, M, ld,
                    s * 32, Klim, tid);
        CP_COMMIT();
    }

    for (int it = 0; it < nIter; it++) {
        CP_WAIT2();
        __syncthreads();
        if (it + 3 < nIter)
            issue_stage(sbase + ((it + 3) & 3) * STAGE_BYTES, Ah, Bh,
                        rowBase, nBase, M, ld, (it + 3) * 32, Klim, tid);
        CP_COMMIT();

        uint32_t stg = sbase + (it & 3) * STAGE_BYTES;
#pragma unroll
        for (int k16 = 0; k16 < 2; k16++) {
            uint32_t ah[2][4], bh[2][4];
#pragma unroll
            for (int mi = 0; mi < 2; mi++) {
                uint32_t off = arow[mi] + ((((uint32_t)(k16 * 2 + cA)) ^ aswz[mi]) << 4);
                ldsm4(ah[mi], stg + OFF_AH + off);
            }
#pragma unroll
            for (int nb = 0; nb < 2; nb++) {
                uint32_t off = brow[nb] + ((((uint32_t)(k16 * 2 + cB)) ^ bswz[nb]) << 4);
                ldsm4(bh[nb], stg + OFF_BH + off);
            }
#pragma unroll
            for (int mi = 0; mi < 2; mi++)
#pragma unroll
                for (int nb = 0; nb < 2; nb++) {
                    mma16816(acc[mi][2 * nb], ah[mi], &bh[nb][0]);
                    mma16816(acc[mi][2 * nb + 1], ah[mi], &bh[nb][2]);
                }
        }
    }

    // ================= Fused epilogue =================
    CP_WAIT0();
    __syncthreads();

    // 1. Store acc -> P fp16 (x AINV). P[64][128], 256B rows, chunk ^ (row&7).
#pragma unroll
    for (int mi = 0; mi < 2; mi++)
#pragma unroll
        for (int h = 0; h < 2; h++) {
            int row = wm * 32 + mi * 16 + (lane >> 2) + h * 8;
#pragma unroll
            for (int ni = 0; ni < 4; ni++) {
                uint32_t c = (uint32_t)(wn * 4 + ni);
                uint32_t off = (uint32_t)row * 256 + ((c ^ (row & 7)) << 4) + (lane & 3) * 4;
                *reinterpret_cast<uint32_t*>(sm + off) =
                    pkf2(acc[mi][ni][2 * h] * AINV, acc[mi][ni][2 * h + 1] * AINV);
            }
        }

    // 2. Stage W[i,nt] fp16, [k][n] rows (256B), chunk ^ (k&7). Coalesced reads.
    {
        int k = tid >> 1, hf = tid & 1;
        const float* wsrc = Wall + (size_t)(ilev * 3 + nt) * DIM * DIM + k * DIM + hf * 64;
#pragma unroll
        for (int j = 0; j < 8; j++) {
            float4 w0 = *reinterpret_cast<const float4*>(wsrc + j * 8);
            float4 w1 = *reinterpret_cast<const float4*>(wsrc + j * 8 + 4);
            uint4 hv;
            hv.x = pkf2(w0.x, w0.y);
            hv.y = pkf2(w0.z, w0.w);
            hv.z = pkf2(w1.x, w1.y);
            hv.w = pkf2(w1.z, w1.w);
            uint32_t c = (uint32_t)(hf * 8 + j);
            *reinterpret_cast<uint4*>(sm + OFF_W + k * 256 + ((c ^ (k & 7)) << 4)) = hv;
        }
    }
    __syncthreads();

    // 3. out_tile = P @ W  (64x128x128), warps: wm x wn as before.
    float ea[2][4][4];
#pragma unroll
    for (int mi = 0; mi < 2; mi++)
#pragma unroll
        for (int ni = 0; ni < 4; ni++)
#pragma unroll
            for (int c = 0; c < 4; c++) ea[mi][ni][c] = 0.f;

    int tile = lane >> 3;
    int l7 = lane & 7;
#pragma unroll
    for (int s = 0; s < 8; s++) {
        uint32_t pa[2][4], bw[2][4];
#pragma unroll
        for (int mi = 0; mi < 2; mi++) {
            int row = wm * 32 + mi * 16 + rA;
            uint32_t c = (uint32_t)(s * 2 + cA);
            ldsm4(pa[mi], sbase + (uint32_t)row * 256 + ((c ^ (row & 7)) << 4));
        }
#pragma unroll
        for (int nb = 0; nb < 2; nb++) {
            int krow = s * 16 + (tile & 1) * 8 + l7;
            uint32_t c = (uint32_t)(wn * 4 + nb * 2 + (tile >> 1));
            ldsm4t(bw[nb], sbase + OFF_W + (uint32_t)krow * 256 + ((c ^ (uint32_t)l7) << 4));
        }
#pragma unroll
        for (int mi = 0; mi < 2; mi++)
#pragma unroll
            for (int nb = 0; nb < 2; nb++) {
                mma16816(ea[mi][2 * nb], pa[mi], &bw[nb][0]);
                mma16816(ea[mi][2 * nb + 1], pa[mi], &bw[nb][2]);
            }
    }

    // 4. bias + relu + store per-j partial (deterministic, disjoint buffers)
    const float* bvec = ball + (size_t)(ilev * 3 + nt) * DIM;
    float* Ej = E + (size_t)nt * M * DIM;
#pragma unroll
    for (int ni = 0; ni < 4; ni++) {
        int col = wn * 32 + ni * 8 + (lane & 3) * 2;
        float2 bb = *reinterpret_cast<const float2*>(bvec + col);
#pragma unroll
        for (int mi = 0; mi < 2; mi++)
#pragma unroll
            for (int h = 0; h < 2; h++) {
                int row = rowBase + wm * 32 + mi * 16 + (lane >> 2) + h * 8;
                if (row < M) {
                    float2 v;
                    v.x = fmaxf(ea[mi][ni][2 * h] + bb.x, 0.f);
                    v.y = fmaxf(ea[mi][ni][2 * h + 1] + bb.y, 0.f);
                    *reinterpret_cast<float2*>(Ej + (size_t)row * DIM + col) = v;
                }
            }
    }
}

// ===========================================================================
// Sum of 3 per-j partials -> out (all levels, one launch)
// ===========================================================================
__global__ void k_sum(const float4* __restrict__ e0, const float4* __restrict__ e1,
                      const float4* __restrict__ e2, float4* __restrict__ out) {
    int i = blockIdx.x * blockDim.x + threadIdx.x;
    int st = gridDim.x * blockDim.x;
    for (int k = i; k < 256000; k += st) {
        float4 a = e0[k], b = e0[k + 256000], c = e0[k + 512000];
        out[k] = make_float4(a.x + b.x + c.x, a.y + b.y + c.y,
                             a.z + b.z + c.z, a.w + b.w + c.w);
    }
    for (int k = i; k < 128000; k += st) {
        float4 a = e1[k], b = e1[k + 128000], c = e1[k + 256000];
        out[256000 + k] = make_float4(a.x + b.x + c.x, a.y + b.y + c.y,
                                      a.z + b.z + c.z, a.w + b.w + c.w);
    }
    for (int k = i; k < 64000; k += st) {
        float4 a = e2[k], b = e2[k + 64000], c = e2[k + 128000];
        out[384000 + k] = make_float4(a.x + b.x + c.x, a.y + b.y + c.y,
                                      a.z + b.z + c.z, a.w + b.w + c.w);
    }
}

// ===========================================================================
extern "C" void kernel_launch(void* const* d_in, const int* in_sizes, int n_in,
                              void* d_out, int out_size) {
    const float* adj0 = (const float*)d_in[0];
    const float* adj1 = (const float*)d_in[1];
    const float* adj2 = (const float*)d_in[2];
    const float* h0 = (const float*)d_in[3];
    const float* h1 = (const float*)d_in[4];
    const float* h2 = (const float*)d_in[5];
    const int* idx0 = (const int*)d_in[6];
    const int* idx1 = (const int*)d_in[7];
    const float* Ws = (const float*)d_in[8];
    const float* bs = (const float*)d_in[9];
    float* out = (float*)d_out;

    __half *Ah0, *Ah1, *Ah2, *Bh0, *Bh1, *Bh2;
    float *E0, *E1, *E2;
    cudaGetSymbolAddress((void**)&Ah0, g_Ah0);
    cudaGetSymbolAddress((void**)&Ah1, g_Ah1);
    cudaGetSymbolAddress((void**)&Ah2, g_Ah2);
    cudaGetSymbolAddress((void**)&Bh0, g_Bh0);
    cudaGetSymbolAddress((void**)&Bh1, g_Bh1);
    cudaGetSymbolAddress((void**)&Bh2, g_Bh2);
    cudaGetSymbolAddress((void**)&E0, g_E0);
    cudaGetSymbolAddress((void**)&E1, g_E1);
    cudaGetSymbolAddress((void**)&E2, g_E2);

    cudaFuncSetAttribute(k_mma, cudaFuncAttributeMaxDynamicSharedMemorySize, SMEM_MMA);

    // Fork: A-conversions on s2; independent B build on main stream.
    cudaStream_t s2;
    cudaStreamCreate(&s2);
    cudaEvent_t evF, evB;
    cudaEventCreateWithFlags(&evF, cudaEventDisableTiming);
    cudaEventCreateWithFlags(&evB, cudaEventDisableTiming);

    cudaEventRecord(evF, 0);
    cudaStreamWaitEvent(s2, evF, 0);

    // s2: adj -> fp16 (scaled)
    k_cvt<<<2048, 256, 0, s2>>>((const float4*)adj0, (uint2*)Ah0,
                                (int)((size_t)N0 * N0 / 4));
    k_cvt<<<1024, 256, 0, s2>>>((const float4*)adj1, (uint2*)Ah1, N1 * N1 / 4);
    k_cvt<<<512, 256, 0, s2>>>((const float4*)adj2, (uint2*)Ah2, N2 * N2 / 4);
    cudaEventRecord(evB, s2);

    // main: B build (overlaps cvt)
    k_zero_all<<<640, 256>>>((float4*)(Bh0 + (size_t)128 * N0),
                             (float4*)(Bh1 + (size_t)256 * N1));
    k_trans_all<<<689, 256>>>(Bh0, Bh1, Bh2, h0, h1, h2, idx0, idx1);
    k_scatter_all<<<4000, 256>>>(Bh0, Bh1, h1, h2, idx0, idx1);

    // join, then GEMM + fused epilogue (660 CTAs)
    cudaStreamWaitEvent(0, evB, 0);
    k_mma<<<660, 256, SMEM_MMA>>>(Ah0, Ah1, Ah2, Bh0, Bh1, Bh2, Ws, bs, E0, E1, E2);

    // sum the 3 per-j partials
    k_sum<<<640, 256>>>((const float4*)E0, (const float4*)E1, (const float4*)E2,
                        (float4*)out);
}